// round 6
// baseline (speedup 1.0000x reference)
#include <cuda_runtime.h>
#include <math.h>
#include <stdint.h>

#define NTOK 2048
#define NB 4
#define DDIM 512
#define D1 1024
#define EDIM 512
#define ROWS (NB * NTOK)   // 8192
#define GAMMA_F 0.999f

// ---------------- scratch (device globals: allocation-free) ----------------
__device__ float g_xn[ROWS * DDIM];
__device__ float g_u [ROWS * D1];
__device__ float g_v [ROWS * D1];
__device__ float g_y [ROWS * D1];
__device__ float g_arr[NTOK * D1];
__device__ float g_h [NTOK * EDIM];
__device__ float g_act[NTOK * EDIM];

// ---------------- helpers ----------------
__device__ __forceinline__ uint32_t to_tf32(float f) {
    uint32_t r;
    asm("cvt.rna.tf32.f32 %0, %1;" : "=r"(r) : "f"(f));
    return r;
}

#define MMA_TF32(ACC, AF, BF)                                                  \
    asm volatile(                                                              \
        "mma.sync.aligned.m16n8k8.row.col.f32.tf32.tf32.f32 "                  \
        "{%0,%1,%2,%3}, {%4,%5,%6,%7}, {%8,%9}, {%0,%1,%2,%3};"               \
        : "+f"((ACC)[0]), "+f"((ACC)[1]), "+f"((ACC)[2]), "+f"((ACC)[3])       \
        : "r"((AF)[0]), "r"((AF)[1]), "r"((AF)[2]), "r"((AF)[3]),              \
          "r"((BF)[0]), "r"((BF)[1]))

#define FFMA2(D, A, B, C)                                                      \
    asm("fma.rn.f32x2 %0, %1, %2, %3;" : "=l"(D) : "l"(A), "l"(B), "l"(C))

// ---------------- sRMS norm (+ optional ReLU), dim = 512 ----------------
template <bool RELU>
__global__ void srms_kernel(const float* __restrict__ in, float* __restrict__ out) {
    int row = blockIdx.x;
    const float4* ip = (const float4*)(in + (size_t)row * 512);
    float4* op = (float4*)(out + (size_t)row * 512);
    int tid = threadIdx.x;                    // 0..127
    float4 val = ip[tid];
    float ss = val.x * val.x + val.y * val.y + val.z * val.z + val.w * val.w;
    #pragma unroll
    for (int o = 16; o > 0; o >>= 1) ss += __shfl_xor_sync(0xffffffffu, ss, o);
    __shared__ float wsum[4];
    if ((tid & 31) == 0) wsum[tid >> 5] = ss;
    __syncthreads();
    float tot = wsum[0] + wsum[1] + wsum[2] + wsum[3];
    float inv = 1.0f / (sqrtf(tot * (1.0f / 512.0f)) + 1e-8f);
    float4 r;
    r.x = val.x * inv; r.y = val.y * inv; r.z = val.z * inv; r.w = val.w * inv;
    if (RELU) {
        r.x = fmaxf(r.x, 0.0f); r.y = fmaxf(r.y, 0.0f);
        r.z = fmaxf(r.z, 0.0f); r.w = fmaxf(r.w, 0.0f);
    }
    op[tid] = r;
}

// ---------------- position embedding ----------------
__global__ void coef0_kernel(const float* __restrict__ Wp, const float* __restrict__ bp,
                             float* __restrict__ out) {
    int t = blockIdx.x;
    int e = threadIdx.x;       // 512 threads
    out[(size_t)t * EDIM + e] = (float)t * Wp[e] + bp[e];
}

// ---------------- tf32 mma.sync GEMM, 128x128x32, 512 threads ----------------
// C[M,N] = A[M,K] @ W[K,N] + bias ; EPI: 0 none, 1 silu, 2 decay, 3 +res
// Smem layout (both A and B): [128 rows][36 words], k-permuted so the
// (t, t+4) fragment pair is adjacent: pos(k) = (k>>3)*8 + (k&3)*2 + ((k>>2)&1).
// A stored by m-row; B stored transposed by n-col.
#define TWRD (128 * 36)                 // words per tile
#define GEMM_SMEM (2 * 2 * TWRD * 4)    // 2 stages x (A + B) = 73728 B

template <int EPI>
__global__ void __launch_bounds__(512)
tf32_gemm_kernel(const float* __restrict__ A, const float* __restrict__ W,
                 const float* __restrict__ bias, const float* __restrict__ res,
                 float* __restrict__ C, int M, int N, int K) {
    extern __shared__ uint32_t sm[];

    int tid = threadIdx.x;             // 512
    int n0 = blockIdx.x * 128;
    int m0 = blockIdx.y * 128;
    int warp = tid >> 5, lane = tid & 31;
    int wm = warp >> 2;                // 0..3  (32-row slab)
    int wn = warp & 3;                 // 0..3  (32-col slab)
    int g = lane >> 2, t = lane & 3;

    float acc[2][4][4];
    #pragma unroll
    for (int mt = 0; mt < 2; mt++)
        #pragma unroll
        for (int nt = 0; nt < 4; nt++)
            #pragma unroll
            for (int e = 0; e < 4; e++) acc[mt][nt][e] = 0.0f;

    // A fill indices: thread -> (row, k-quarter)
    int ar = tid >> 2;                 // 0..127
    int aq = tid & 3;                  // 0..3 (8 k's each)
    // B fill indices: thread -> (col, k-quarter)
    int bcol = tid & 127;
    int bq = tid >> 7;                 // 0..3

    // prefetch chunk 0
    float4 a0 = *(const float4*)(A + (size_t)(m0 + ar) * K + aq * 8);
    float4 a1 = *(const float4*)(A + (size_t)(m0 + ar) * K + aq * 8 + 4);
    float bv[8];
    {
        const float* Wb = W + (size_t)(bq * 8) * N + n0 + bcol;
        #pragma unroll
        for (int j = 0; j < 8; j++) bv[j] = Wb[(size_t)j * N];
    }

    int nch = K >> 5;
    #pragma unroll 1
    for (int i = 0; i < nch; i++) {
        int s = i & 1;
        uint32_t* As = sm + s * 2 * TWRD;
        uint32_t* Bs = As + TWRD;

        // store A (k-permuted): [a0.x,a1.x,a0.y,a1.y] then [a0.z,a1.z,a0.w,a1.w]
        {
            uint32_t* p = &As[ar * 36 + aq * 8];
            uint4 lo = make_uint4(to_tf32(a0.x), to_tf32(a1.x), to_tf32(a0.y), to_tf32(a1.y));
            uint4 hi = make_uint4(to_tf32(a0.z), to_tf32(a1.z), to_tf32(a0.w), to_tf32(a1.w));
            *(uint4*)(p) = lo;
            *(uint4*)(p + 4) = hi;
        }
        // store B transposed (k-permuted): [b0,b4,b1,b5] then [b2,b6,b3,b7]
        {
            uint32_t* p = &Bs[bcol * 36 + bq * 8];
            uint4 lo = make_uint4(to_tf32(bv[0]), to_tf32(bv[4]), to_tf32(bv[1]), to_tf32(bv[5]));
            uint4 hi = make_uint4(to_tf32(bv[2]), to_tf32(bv[6]), to_tf32(bv[3]), to_tf32(bv[7]));
            *(uint4*)(p) = lo;
            *(uint4*)(p + 4) = hi;
        }
        __syncthreads();

        // prefetch next chunk while MMAs run
        int kn = (i + 1) << 5;
        if (kn < K) {
            a0 = *(const float4*)(A + (size_t)(m0 + ar) * K + kn + aq * 8);
            a1 = *(const float4*)(A + (size_t)(m0 + ar) * K + kn + aq * 8 + 4);
            const float* Wb = W + (size_t)(kn + bq * 8) * N + n0 + bcol;
            #pragma unroll
            for (int j = 0; j < 8; j++) bv[j] = Wb[(size_t)j * N];
        }

        #pragma unroll
        for (int ks = 0; ks < 4; ks++) {
            int kb = ks * 8 + 2 * t;
            uint32_t af[2][4], bf[4][2];
            #pragma unroll
            for (int mt = 0; mt < 2; mt++) {
                int row = wm * 32 + mt * 16 + g;
                uint2 pL = *(const uint2*)(&As[row * 36 + kb]);
                uint2 pH = *(const uint2*)(&As[(row + 8) * 36 + kb]);
                af[mt][0] = pL.x; af[mt][1] = pH.x;
                af[mt][2] = pL.y; af[mt][3] = pH.y;
            }
            #pragma unroll
            for (int nt = 0; nt < 4; nt++) {
                int col = wn * 32 + nt * 8 + g;
                uint2 q = *(const uint2*)(&Bs[col * 36 + kb]);
                bf[nt][0] = q.x; bf[nt][1] = q.y;
            }
            #pragma unroll
            for (int mt = 0; mt < 2; mt++)
                #pragma unroll
                for (int nt = 0; nt < 4; nt++)
                    MMA_TF32(acc[mt][nt], af[mt], bf[nt]);
        }
        __syncthreads();
    }

    float lg = logf(GAMMA_F);
    #pragma unroll
    for (int mt = 0; mt < 2; mt++) {
        int mrow0 = m0 + wm * 32 + mt * 16 + g;
        #pragma unroll
        for (int h2 = 0; h2 < 2; h2++) {
            int m = mrow0 + 8 * h2;
            float dec = 1.0f;
            if (EPI == 2) dec = (m == 0) ? 1.0f : expf((float)m * lg);
            #pragma unroll
            for (int nt = 0; nt < 4; nt++) {
                int n = n0 + wn * 32 + nt * 8 + 2 * t;
                float v0 = acc[mt][nt][2 * h2 + 0] + bias[n];
                float v1 = acc[mt][nt][2 * h2 + 1] + bias[n + 1];
                if (EPI == 1) {
                    v0 = v0 / (1.0f + expf(-v0));
                    v1 = v1 / (1.0f + expf(-v1));
                }
                if (EPI == 2) { v0 *= dec; v1 *= dec; }
                if (EPI == 3) {
                    float2 rv = *(const float2*)(res + (size_t)m * N + n);
                    v0 += rv.x; v1 += rv.y;
                }
                *(float2*)(C + (size_t)m * N + n) = make_float2(v0, v1);
            }
        }
    }
}

// ---------------- causal depthwise Toeplitz conv + gate (packed f32x2) -------
#define CONV_SMEM ((64 * 64 + 192 * 64) * 4)

__global__ void __launch_bounds__(256)
conv_kernel(const float* __restrict__ v, const float* __restrict__ arr,
            const float* __restrict__ u, float* __restrict__ y) {
    extern __shared__ float cs[];
    float* a_s = cs;              // [64][64]
    float* v_s = cs + 64 * 64;    // [192][64]

    int b = blockIdx.z;
    int c0 = blockIdx.y * 64;
    int iblk = (gridDim.x - 1) - blockIdx.x;   // heaviest tiles first
    int t0 = iblk * 128;
    int tid = threadIdx.x;                     // 256
    int tx = tid & 15;                         // c group (4 channels)
    int ty = tid >> 4;                         // t group (8 rows)

    unsigned long long acc2[8][2];
    #pragma unroll
    for (int i = 0; i < 8; i++) { acc2[i][0] = 0ULL; acc2[i][1] = 0ULL; }

    const float* vb = v + (size_t)b * NTOK * D1;
    int nch = 2 * iblk + 2;

    for (int jb = 0; jb < nch; jb++) {
        __syncthreads();
        #pragma unroll
        for (int it = 0; it < 4; it++) {
            int idx = it * 256 + tid;
            int rq = idx >> 4;
            int cseg = idx & 15;
            float4 val = *(const float4*)(arr + (size_t)(jb * 64 + rq) * D1 + c0 + cseg * 4);
            *(float4*)(&a_s[rq * 64 + cseg * 4]) = val;
        }
        int gbase = t0 - jb * 64 - 63;
        #pragma unroll
        for (int it = 0; it < 12; it++) {
            int idx = it * 256 + tid;
            int rl = idx >> 4;
            int cseg = idx & 15;
            int gg = gbase + rl;
            float4 val = make_float4(0.0f, 0.0f, 0.0f, 0.0f);
            if (gg >= 0 && gg < NTOK)
                val = *(const float4*)(vb + (size_t)gg * D1 + c0 + cseg * 4);
            *(float4*)(&v_s[rl * 64 + cseg * 4]) = val;
        }
        __syncthreads();

        unsigned long long w2[8][2];
        #pragma unroll
        for (int i = 0; i < 8; i++) {
            ulonglong2 wv = *(const ulonglong2*)(&v_s[(63 + ty * 8 + i) * 64 + tx * 4]);
            w2[i][0] = wv.x; w2[i][1] = wv.y;
        }

        #pragma unroll 8
        for (int q = 0; q < 64; q++) {
            ulonglong2 a2 = *(const ulonglong2*)(&a_s[q * 64 + tx * 4]);
            #pragma unroll
            for (int i = 0; i < 8; i++) {
                FFMA2(acc2[i][0], a2.x, w2[i][0], acc2[i][0]);
                FFMA2(acc2[i][1], a2.y, w2[i][1], acc2[i][1]);
            }
            if (q < 63) {
                #pragma unroll
                for (int i = 7; i > 0; i--) { w2[i][0] = w2[i - 1][0]; w2[i][1] = w2[i - 1][1]; }
                ulonglong2 wv = *(const ulonglong2*)(&v_s[(62 + ty * 8 - q) * 64 + tx * 4]);
                w2[0][0] = wv.x; w2[0][1] = wv.y;
            }
        }
    }

    #pragma unroll
    for (int i = 0; i < 8; i++) {
        int t = t0 + ty * 8 + i;
        size_t off = ((size_t)b * NTOK + t) * D1 + c0 + tx * 4;
        float4 uv = *(const float4*)(u + off);
        float2 lo = *(float2*)(&acc2[i][0]);
        float2 hi = *(float2*)(&acc2[i][1]);
        float4 o;
        o.x = uv.x * lo.x;
        o.y = uv.y * lo.y;
        o.z = uv.z * hi.x;
        o.w = uv.w * hi.y;
        *(float4*)(y + off) = o;
    }
}

// ---------------- launch ----------------
extern "C" void kernel_launch(void* const* d_in, const int* in_sizes, int n_in,
                              void* d_out, int out_size) {
    const float* x  = (const float*)d_in[0];
    const float* Wu = (const float*)d_in[1];
    const float* bu = (const float*)d_in[2];
    const float* Wv = (const float*)d_in[3];
    const float* bv = (const float*)d_in[4];
    const float* Wo = (const float*)d_in[5];
    const float* bo = (const float*)d_in[6];
    const float* Wp = (const float*)d_in[7];
    const float* bp = (const float*)d_in[8];
    const float* W1 = (const float*)d_in[9];
    const float* b1 = (const float*)d_in[10];
    const float* W2 = (const float*)d_in[11];
    const float* b2 = (const float*)d_in[12];
    const float* W3 = (const float*)d_in[13];
    const float* b3 = (const float*)d_in[14];
    const float* Wz = (const float*)d_in[15];
    const float* bz = (const float*)d_in[16];
    float* out = (float*)d_out;

    float *xn, *u, *v, *y, *arr, *h, *act;
    cudaGetSymbolAddress((void**)&xn,  g_xn);
    cudaGetSymbolAddress((void**)&u,   g_u);
    cudaGetSymbolAddress((void**)&v,   g_v);
    cudaGetSymbolAddress((void**)&y,   g_y);
    cudaGetSymbolAddress((void**)&arr, g_arr);
    cudaGetSymbolAddress((void**)&h,   g_h);
    cudaGetSymbolAddress((void**)&act, g_act);

    cudaFuncSetAttribute(tf32_gemm_kernel<0>, cudaFuncAttributeMaxDynamicSharedMemorySize, GEMM_SMEM);
    cudaFuncSetAttribute(tf32_gemm_kernel<1>, cudaFuncAttributeMaxDynamicSharedMemorySize, GEMM_SMEM);
    cudaFuncSetAttribute(tf32_gemm_kernel<2>, cudaFuncAttributeMaxDynamicSharedMemorySize, GEMM_SMEM);
    cudaFuncSetAttribute(tf32_gemm_kernel<3>, cudaFuncAttributeMaxDynamicSharedMemorySize, GEMM_SMEM);
    cudaFuncSetAttribute(conv_kernel,         cudaFuncAttributeMaxDynamicSharedMemorySize, CONV_SMEM);

    // main path norm
    srms_kernel<false><<<ROWS, 128>>>(x, xn);

    // u, v projections with SiLU (tf32 tensor cores)
    tf32_gemm_kernel<1><<<dim3(D1 / 128, ROWS / 128), 512, GEMM_SMEM>>>(xn, Wu, bu, nullptr, u, ROWS, D1, DDIM);
    tf32_gemm_kernel<1><<<dim3(D1 / 128, ROWS / 128), 512, GEMM_SMEM>>>(xn, Wv, bv, nullptr, v, ROWS, D1, DDIM);

    // coefficient MLP (position-only)
    coef0_kernel<<<NTOK, EDIM>>>(Wp, bp, h);
    srms_kernel<true><<<NTOK, 128>>>(h, act);
    tf32_gemm_kernel<0><<<dim3(EDIM / 128, NTOK / 128), 512, GEMM_SMEM>>>(act, W1, b1, nullptr, h, NTOK, EDIM, EDIM);
    srms_kernel<true><<<NTOK, 128>>>(h, act);
    tf32_gemm_kernel<0><<<dim3(EDIM / 128, NTOK / 128), 512, GEMM_SMEM>>>(act, W2, b2, nullptr, h, NTOK, EDIM, EDIM);
    srms_kernel<true><<<NTOK, 128>>>(h, act);
    tf32_gemm_kernel<0><<<dim3(EDIM / 128, NTOK / 128), 512, GEMM_SMEM>>>(act, W3, b3, nullptr, h, NTOK, EDIM, EDIM);
    srms_kernel<true><<<NTOK, 128>>>(h, act);
    // final coef layer with decay applied in epilogue -> arr[r, c]
    tf32_gemm_kernel<2><<<dim3(D1 / 128, NTOK / 128), 512, GEMM_SMEM>>>(act, Wz, bz, nullptr, arr, NTOK, D1, EDIM);

    // causal depthwise Toeplitz conv, gated by u (packed f32x2 FMA)
    conv_kernel<<<dim3(NTOK / 128, D1 / 64, NB), 256, CONV_SMEM>>>(v, arr, u, y);

    // output projection + bias + residual
    tf32_gemm_kernel<3><<<dim3(DDIM / 128, ROWS / 128), 512, GEMM_SMEM>>>(y, Wo, bo, x, out, ROWS, DDIM, D1);
}

// round 7
// speedup vs baseline: 1.2497x; 1.2497x over previous
#include <cuda_runtime.h>
#include <cuda_fp16.h>
#include <math.h>
#include <stdint.h>

#define NTOK 2048
#define NB 4
#define DDIM 512
#define D1 1024
#define EDIM 512
#define ROWS (NB * NTOK)   // 8192
#define GAMMA_F 0.999f

// ---------------- scratch (device globals: allocation-free) ----------------
__device__ float g_xn[ROWS * DDIM];
__device__ float g_u [ROWS * D1];
__device__ float g_v [ROWS * D1];
__device__ float g_y [ROWS * D1];
__device__ float g_arr[NTOK * D1];
__device__ float g_h [NTOK * EDIM];
__device__ float g_act[NTOK * EDIM];

// ---------------- helpers ----------------
__device__ __forceinline__ uint32_t pack_h2(float a, float b) {
    __half2 h = __floats2half2_rn(a, b);
    return *(uint32_t*)&h;
}

#define MMA_F16(ACC, AF, BF)                                                   \
    asm volatile(                                                              \
        "mma.sync.aligned.m16n8k16.row.col.f32.f16.f16.f32 "                   \
        "{%0,%1,%2,%3}, {%4,%5,%6,%7}, {%8,%9}, {%0,%1,%2,%3};"               \
        : "+f"((ACC)[0]), "+f"((ACC)[1]), "+f"((ACC)[2]), "+f"((ACC)[3])       \
        : "r"((AF)[0]), "r"((AF)[1]), "r"((AF)[2]), "r"((AF)[3]),              \
          "r"((BF)[0]), "r"((BF)[1]))

#define FFMA2(D, A, B, C)                                                      \
    asm("fma.rn.f32x2 %0, %1, %2, %3;" : "=l"(D) : "l"(A), "l"(B), "l"(C))

// ---------------- sRMS norm (+ optional ReLU), dim = 512 ----------------
template <bool RELU>
__global__ void srms_kernel(const float* __restrict__ in, float* __restrict__ out) {
    int row = blockIdx.x;
    const float4* ip = (const float4*)(in + (size_t)row * 512);
    float4* op = (float4*)(out + (size_t)row * 512);
    int tid = threadIdx.x;                    // 0..127
    float4 val = ip[tid];
    float ss = val.x * val.x + val.y * val.y + val.z * val.z + val.w * val.w;
    #pragma unroll
    for (int o = 16; o > 0; o >>= 1) ss += __shfl_xor_sync(0xffffffffu, ss, o);
    __shared__ float wsum[4];
    if ((tid & 31) == 0) wsum[tid >> 5] = ss;
    __syncthreads();
    float tot = wsum[0] + wsum[1] + wsum[2] + wsum[3];
    float inv = 1.0f / (sqrtf(tot * (1.0f / 512.0f)) + 1e-8f);
    float4 r;
    r.x = val.x * inv; r.y = val.y * inv; r.z = val.z * inv; r.w = val.w * inv;
    if (RELU) {
        r.x = fmaxf(r.x, 0.0f); r.y = fmaxf(r.y, 0.0f);
        r.z = fmaxf(r.z, 0.0f); r.w = fmaxf(r.w, 0.0f);
    }
    op[tid] = r;
}

// ---------------- position embedding ----------------
__global__ void coef0_kernel(const float* __restrict__ Wp, const float* __restrict__ bp,
                             float* __restrict__ out) {
    int t = blockIdx.x;
    int e = threadIdx.x;       // 512 threads
    out[(size_t)t * EDIM + e] = (float)t * Wp[e] + bp[e];
}

// ---------------- fp16 mma.sync GEMM, 128x128x32, 256 threads ----------------
// C[M,N] = A[M,K] @ W[K,N] + bias ; EPI: 0 none, 1 silu, 2 decay, 3 +res
// Smem: packed half2 words, row stride 20 (16 used + 4 pad) -> conflict-free.
// A: As[row][kw]  (row = m)   B: Bs[col][kw] (col = n, transposed fill)
#define TSTR 20
#define TWRD (128 * TSTR)               // words per tile
#define GEMM_SMEM (2 * 2 * TWRD * 4)    // 2 stages x (A+B) = 40960 B

template <int EPI>
__global__ void __launch_bounds__(256)
hgemm_kernel(const float* __restrict__ A, const float* __restrict__ W,
             const float* __restrict__ bias, const float* __restrict__ res,
             float* __restrict__ C, int M, int N, int K) {
    extern __shared__ uint32_t sm[];

    int tid = threadIdx.x;             // 256
    int n0 = blockIdx.x * 128;
    int m0 = blockIdx.y * 128;
    int warp = tid >> 5, lane = tid & 31;
    int wm = warp >> 2;                // 0..1  (64-row slab)
    int wn = warp & 3;                 // 0..3  (32-col slab)
    int g = lane >> 2, t = lane & 3;

    float acc[4][4][4];
    #pragma unroll
    for (int mt = 0; mt < 4; mt++)
        #pragma unroll
        for (int nt = 0; nt < 4; nt++)
            #pragma unroll
            for (int e = 0; e < 4; e++) acc[mt][nt][e] = 0.0f;

    // A fill: thread -> (row ar, k-half aseg); 16 contiguous floats
    int ar = tid >> 1;                 // 0..127
    int aseg = tid & 1;                // 0/1 -> k 0-15 / 16-31
    // B fill: thread -> (col bn, k-half bkh); 16 strided floats (coalesced in n)
    int bn = tid & 127;
    int bkh = tid >> 7;                // 0/1

    // prefetch chunk 0
    float4 av[4];
    #pragma unroll
    for (int j = 0; j < 4; j++)
        av[j] = *(const float4*)(A + (size_t)(m0 + ar) * K + aseg * 16 + 4 * j);
    float bvv[16];
    {
        const float* Wb = W + (size_t)(bkh * 16) * N + n0 + bn;
        #pragma unroll
        for (int j = 0; j < 16; j++) bvv[j] = Wb[(size_t)j * N];
    }

    int nch = K >> 5;
    #pragma unroll 1
    for (int i = 0; i < nch; i++) {
        int s = i & 1;
        uint32_t* As = sm + s * 2 * TWRD;
        uint32_t* Bs = As + TWRD;

        // store A: 8 packed words
        {
            uint32_t* p = &As[ar * TSTR + aseg * 8];
            uint4 lo = make_uint4(pack_h2(av[0].x, av[0].y), pack_h2(av[0].z, av[0].w),
                                  pack_h2(av[1].x, av[1].y), pack_h2(av[1].z, av[1].w));
            uint4 hi = make_uint4(pack_h2(av[2].x, av[2].y), pack_h2(av[2].z, av[2].w),
                                  pack_h2(av[3].x, av[3].y), pack_h2(av[3].z, av[3].w));
            *(uint4*)(p) = lo;
            *(uint4*)(p + 4) = hi;
        }
        // store B transposed: 8 packed words
        {
            uint32_t* p = &Bs[bn * TSTR + bkh * 8];
            uint4 lo = make_uint4(pack_h2(bvv[0], bvv[1]),  pack_h2(bvv[2], bvv[3]),
                                  pack_h2(bvv[4], bvv[5]),  pack_h2(bvv[6], bvv[7]));
            uint4 hi = make_uint4(pack_h2(bvv[8], bvv[9]),  pack_h2(bvv[10], bvv[11]),
                                  pack_h2(bvv[12], bvv[13]), pack_h2(bvv[14], bvv[15]));
            *(uint4*)(p) = lo;
            *(uint4*)(p + 4) = hi;
        }
        __syncthreads();

        // prefetch next chunk while MMAs run
        int kn = (i + 1) << 5;
        if (kn < K) {
            #pragma unroll
            for (int j = 0; j < 4; j++)
                av[j] = *(const float4*)(A + (size_t)(m0 + ar) * K + kn + aseg * 16 + 4 * j);
            const float* Wb = W + (size_t)(kn + bkh * 16) * N + n0 + bn;
            #pragma unroll
            for (int j = 0; j < 16; j++) bvv[j] = Wb[(size_t)j * N];
        }

        // 2 k-steps of k16
        #pragma unroll
        for (int ks = 0; ks < 2; ks++) {
            int kw = ks * 8;
            uint32_t af[4][4], bf[4][2];
            #pragma unroll
            for (int mt = 0; mt < 4; mt++) {
                int row = wm * 64 + mt * 16 + g;
                af[mt][0] = As[row * TSTR + kw + t];
                af[mt][1] = As[(row + 8) * TSTR + kw + t];
                af[mt][2] = As[row * TSTR + kw + t + 4];
                af[mt][3] = As[(row + 8) * TSTR + kw + t + 4];
            }
            #pragma unroll
            for (int nt = 0; nt < 4; nt++) {
                int col = wn * 32 + nt * 8 + g;
                bf[nt][0] = Bs[col * TSTR + kw + t];
                bf[nt][1] = Bs[col * TSTR + kw + t + 4];
            }
            #pragma unroll
            for (int mt = 0; mt < 4; mt++)
                #pragma unroll
                for (int nt = 0; nt < 4; nt++)
                    MMA_F16(acc[mt][nt], af[mt], bf[nt]);
        }
    }

    float lg = logf(GAMMA_F);
    #pragma unroll
    for (int mt = 0; mt < 4; mt++) {
        int mrow0 = m0 + wm * 64 + mt * 16 + g;
        #pragma unroll
        for (int h2 = 0; h2 < 2; h2++) {
            int m = mrow0 + 8 * h2;
            float dec = 1.0f;
            if (EPI == 2) dec = (m == 0) ? 1.0f : expf((float)m * lg);
            #pragma unroll
            for (int nt = 0; nt < 4; nt++) {
                int n = n0 + wn * 32 + nt * 8 + 2 * t;
                float v0 = acc[mt][nt][2 * h2 + 0] + bias[n];
                float v1 = acc[mt][nt][2 * h2 + 1] + bias[n + 1];
                if (EPI == 1) {
                    v0 = v0 / (1.0f + expf(-v0));
                    v1 = v1 / (1.0f + expf(-v1));
                }
                if (EPI == 2) { v0 *= dec; v1 *= dec; }
                if (EPI == 3) {
                    float2 rv = *(const float2*)(res + (size_t)m * N + n);
                    v0 += rv.x; v1 += rv.y;
                }
                *(float2*)(C + (size_t)m * N + n) = make_float2(v0, v1);
            }
        }
    }
}

// ---------------- causal depthwise Toeplitz conv + gate (packed f32x2) -------
#define CONV_SMEM ((64 * 64 + 192 * 64) * 4)

__global__ void __launch_bounds__(256)
conv_kernel(const float* __restrict__ v, const float* __restrict__ arr,
            const float* __restrict__ u, float* __restrict__ y) {
    extern __shared__ float cs[];
    float* a_s = cs;              // [64][64]
    float* v_s = cs + 64 * 64;    // [192][64]

    int b = blockIdx.z;
    int c0 = blockIdx.y * 64;
    int iblk = (gridDim.x - 1) - blockIdx.x;   // heaviest tiles first
    int t0 = iblk * 128;
    int tid = threadIdx.x;                     // 256
    int tx = tid & 15;                         // c group (4 channels)
    int ty = tid >> 4;                         // t group (8 rows)

    unsigned long long acc2[8][2];
    #pragma unroll
    for (int i = 0; i < 8; i++) { acc2[i][0] = 0ULL; acc2[i][1] = 0ULL; }

    const float* vb = v + (size_t)b * NTOK * D1;
    int nch = 2 * iblk + 2;

    for (int jb = 0; jb < nch; jb++) {
        __syncthreads();
        #pragma unroll
        for (int it = 0; it < 4; it++) {
            int idx = it * 256 + tid;
            int rq = idx >> 4;
            int cseg = idx & 15;
            float4 val = *(const float4*)(arr + (size_t)(jb * 64 + rq) * D1 + c0 + cseg * 4);
            *(float4*)(&a_s[rq * 64 + cseg * 4]) = val;
        }
        int gbase = t0 - jb * 64 - 63;
        #pragma unroll
        for (int it = 0; it < 12; it++) {
            int idx = it * 256 + tid;
            int rl = idx >> 4;
            int cseg = idx & 15;
            int gg = gbase + rl;
            float4 val = make_float4(0.0f, 0.0f, 0.0f, 0.0f);
            if (gg >= 0 && gg < NTOK)
                val = *(const float4*)(vb + (size_t)gg * D1 + c0 + cseg * 4);
            *(float4*)(&v_s[rl * 64 + cseg * 4]) = val;
        }
        __syncthreads();

        unsigned long long w2[8][2];
        #pragma unroll
        for (int i = 0; i < 8; i++) {
            ulonglong2 wv = *(const ulonglong2*)(&v_s[(63 + ty * 8 + i) * 64 + tx * 4]);
            w2[i][0] = wv.x; w2[i][1] = wv.y;
        }

        #pragma unroll 8
        for (int q = 0; q < 64; q++) {
            ulonglong2 a2 = *(const ulonglong2*)(&a_s[q * 64 + tx * 4]);
            #pragma unroll
            for (int i = 0; i < 8; i++) {
                FFMA2(acc2[i][0], a2.x, w2[i][0], acc2[i][0]);
                FFMA2(acc2[i][1], a2.y, w2[i][1], acc2[i][1]);
            }
            if (q < 63) {
                #pragma unroll
                for (int i = 7; i > 0; i--) { w2[i][0] = w2[i - 1][0]; w2[i][1] = w2[i - 1][1]; }
                ulonglong2 wv = *(const ulonglong2*)(&v_s[(62 + ty * 8 - q) * 64 + tx * 4]);
                w2[0][0] = wv.x; w2[0][1] = wv.y;
            }
        }
    }

    #pragma unroll
    for (int i = 0; i < 8; i++) {
        int t = t0 + ty * 8 + i;
        size_t off = ((size_t)b * NTOK + t) * D1 + c0 + tx * 4;
        float4 uv = *(const float4*)(u + off);
        float2 lo = *(float2*)(&acc2[i][0]);
        float2 hi = *(float2*)(&acc2[i][1]);
        float4 o;
        o.x = uv.x * lo.x;
        o.y = uv.y * lo.y;
        o.z = uv.z * hi.x;
        o.w = uv.w * hi.y;
        *(float4*)(y + off) = o;
    }
}

// ---------------- launch ----------------
extern "C" void kernel_launch(void* const* d_in, const int* in_sizes, int n_in,
                              void* d_out, int out_size) {
    const float* x  = (const float*)d_in[0];
    const float* Wu = (const float*)d_in[1];
    const float* bu = (const float*)d_in[2];
    const float* Wv = (const float*)d_in[3];
    const float* bv = (const float*)d_in[4];
    const float* Wo = (const float*)d_in[5];
    const float* bo = (const float*)d_in[6];
    const float* Wp = (const float*)d_in[7];
    const float* bp = (const float*)d_in[8];
    const float* W1 = (const float*)d_in[9];
    const float* b1 = (const float*)d_in[10];
    const float* W2 = (const float*)d_in[11];
    const float* b2 = (const float*)d_in[12];
    const float* W3 = (const float*)d_in[13];
    const float* b3 = (const float*)d_in[14];
    const float* Wz = (const float*)d_in[15];
    const float* bz = (const float*)d_in[16];
    float* out = (float*)d_out;

    float *xn, *u, *v, *y, *arr, *h, *act;
    cudaGetSymbolAddress((void**)&xn,  g_xn);
    cudaGetSymbolAddress((void**)&u,   g_u);
    cudaGetSymbolAddress((void**)&v,   g_v);
    cudaGetSymbolAddress((void**)&y,   g_y);
    cudaGetSymbolAddress((void**)&arr, g_arr);
    cudaGetSymbolAddress((void**)&h,   g_h);
    cudaGetSymbolAddress((void**)&act, g_act);

    cudaFuncSetAttribute(hgemm_kernel<0>, cudaFuncAttributeMaxDynamicSharedMemorySize, GEMM_SMEM);
    cudaFuncSetAttribute(hgemm_kernel<1>, cudaFuncAttributeMaxDynamicSharedMemorySize, GEMM_SMEM);
    cudaFuncSetAttribute(hgemm_kernel<2>, cudaFuncAttributeMaxDynamicSharedMemorySize, GEMM_SMEM);
    cudaFuncSetAttribute(hgemm_kernel<3>, cudaFuncAttributeMaxDynamicSharedMemorySize, GEMM_SMEM);
    cudaFuncSetAttribute(conv_kernel,     cudaFuncAttributeMaxDynamicSharedMemorySize, CONV_SMEM);

    // main path norm
    srms_kernel<false><<<ROWS, 128>>>(x, xn);

    // u, v projections with SiLU (fp16 tensor cores)
    hgemm_kernel<1><<<dim3(D1 / 128, ROWS / 128), 256, GEMM_SMEM>>>(xn, Wu, bu, nullptr, u, ROWS, D1, DDIM);
    hgemm_kernel<1><<<dim3(D1 / 128, ROWS / 128), 256, GEMM_SMEM>>>(xn, Wv, bv, nullptr, v, ROWS, D1, DDIM);

    // coefficient MLP (position-only)
    coef0_kernel<<<NTOK, EDIM>>>(Wp, bp, h);
    srms_kernel<true><<<NTOK, 128>>>(h, act);
    hgemm_kernel<0><<<dim3(EDIM / 128, NTOK / 128), 256, GEMM_SMEM>>>(act, W1, b1, nullptr, h, NTOK, EDIM, EDIM);
    srms_kernel<true><<<NTOK, 128>>>(h, act);
    hgemm_kernel<0><<<dim3(EDIM / 128, NTOK / 128), 256, GEMM_SMEM>>>(act, W2, b2, nullptr, h, NTOK, EDIM, EDIM);
    srms_kernel<true><<<NTOK, 128>>>(h, act);
    hgemm_kernel<0><<<dim3(EDIM / 128, NTOK / 128), 256, GEMM_SMEM>>>(act, W3, b3, nullptr, h, NTOK, EDIM, EDIM);
    srms_kernel<true><<<NTOK, 128>>>(h, act);
    // final coef layer with decay applied in epilogue -> arr[r, c]
    hgemm_kernel<2><<<dim3(D1 / 128, NTOK / 128), 256, GEMM_SMEM>>>(act, Wz, bz, nullptr, arr, NTOK, D1, EDIM);

    // causal depthwise Toeplitz conv, gated by u (packed f32x2 FMA)
    conv_kernel<<<dim3(NTOK / 128, D1 / 64, NB), 256, CONV_SMEM>>>(v, arr, u, y);

    // output projection + bias + residual
    hgemm_kernel<3><<<dim3(DDIM / 128, ROWS / 128), 256, GEMM_SMEM>>>(y, Wo, bo, x, out, ROWS, DDIM, D1);
}

// round 8
// speedup vs baseline: 1.3814x; 1.1054x over previous
#include <cuda_runtime.h>
#include <cuda_fp16.h>
#include <math.h>
#include <stdint.h>

#define NTOK 2048
#define NB 4
#define DDIM 512
#define D1 1024
#define EDIM 512
#define ROWS (NB * NTOK)   // 8192
#define GAMMA_F 0.999f

// ---------------- scratch (device globals: allocation-free) ----------------
__device__ float  g_u  [ROWS * D1];
__device__ float  g_v  [ROWS * D1];
__device__ float  g_arr[NTOK * D1];
__device__ float  g_h  [NTOK * EDIM];
__device__ __half g_xnh [ROWS * DDIM];
__device__ __half g_acth[NTOK * EDIM];
__device__ __half g_yh  [ROWS * D1];
__device__ __half g_Wuh[DDIM * D1];
__device__ __half g_Wvh[DDIM * D1];
__device__ __half g_Woh[D1 * DDIM];
__device__ __half g_W1h[EDIM * EDIM];
__device__ __half g_W2h[EDIM * EDIM];
__device__ __half g_W3h[EDIM * EDIM];
__device__ __half g_Wzh[EDIM * D1];

// ---------------- helpers ----------------
__device__ __forceinline__ uint32_t smem_u32(const void* p) {
    uint32_t a;
    asm("{ .reg .u64 t; cvta.to.shared.u64 t, %1; cvt.u32.u64 %0, t; }" : "=r"(a) : "l"(p));
    return a;
}

#define MMA_F16(ACC, AF, BF)                                                   \
    asm volatile(                                                              \
        "mma.sync.aligned.m16n8k16.row.col.f32.f16.f16.f32 "                   \
        "{%0,%1,%2,%3}, {%4,%5,%6,%7}, {%8,%9}, {%0,%1,%2,%3};"               \
        : "+f"((ACC)[0]), "+f"((ACC)[1]), "+f"((ACC)[2]), "+f"((ACC)[3])       \
        : "r"((AF)[0]), "r"((AF)[1]), "r"((AF)[2]), "r"((AF)[3]),              \
          "r"((BF)[0]), "r"((BF)[1]))

#define LDSM_X4(R0, R1, R2, R3, A)                                             \
    asm volatile("ldmatrix.sync.aligned.m8n8.x4.shared.b16 {%0,%1,%2,%3}, [%4];" \
        : "=r"(R0), "=r"(R1), "=r"(R2), "=r"(R3) : "r"(A))

#define LDSM_X4T(R0, R1, R2, R3, A)                                            \
    asm volatile("ldmatrix.sync.aligned.m8n8.x4.trans.shared.b16 {%0,%1,%2,%3}, [%4];" \
        : "=r"(R0), "=r"(R1), "=r"(R2), "=r"(R3) : "r"(A))

#define CP_ASYNC16(DST, SRC)                                                   \
    asm volatile("cp.async.cg.shared.global [%0], [%1], 16;" :: "r"(DST), "l"(SRC))
#define CP_COMMIT() asm volatile("cp.async.commit_group;" ::: "memory")
#define CP_WAIT1()  asm volatile("cp.async.wait_group 1;" ::: "memory")

#define FFMA2(D, A, B, C)                                                      \
    asm("fma.rn.f32x2 %0, %1, %2, %3;" : "=l"(D) : "l"(A), "l"(B), "l"(C))

// ---------------- fp32 -> fp16 convert ----------------
__global__ void f2h_kernel(const float* __restrict__ in, __half* __restrict__ out, int n) {
    int i = (blockIdx.x * 256 + threadIdx.x) * 4;
    if (i < n) {
        float4 vv = *(const float4*)(in + i);
        __half2 a = __floats2half2_rn(vv.x, vv.y);
        __half2 b = __floats2half2_rn(vv.z, vv.w);
        *(uint2*)(out + i) = make_uint2(*(uint32_t*)&a, *(uint32_t*)&b);
    }
}

// ---------------- sRMS norm (+ optional ReLU), dim = 512, fp16 out ----------
template <bool RELU>
__global__ void srms_kernel(const float* __restrict__ in, __half* __restrict__ out) {
    int row = blockIdx.x;
    const float4* ip = (const float4*)(in + (size_t)row * 512);
    int tid = threadIdx.x;                    // 0..127
    float4 val = ip[tid];
    float ss = val.x * val.x + val.y * val.y + val.z * val.z + val.w * val.w;
    #pragma unroll
    for (int o = 16; o > 0; o >>= 1) ss += __shfl_xor_sync(0xffffffffu, ss, o);
    __shared__ float wsum[4];
    if ((tid & 31) == 0) wsum[tid >> 5] = ss;
    __syncthreads();
    float tot = wsum[0] + wsum[1] + wsum[2] + wsum[3];
    float inv = 1.0f / (sqrtf(tot * (1.0f / 512.0f)) + 1e-8f);
    float4 r;
    r.x = val.x * inv; r.y = val.y * inv; r.z = val.z * inv; r.w = val.w * inv;
    if (RELU) {
        r.x = fmaxf(r.x, 0.0f); r.y = fmaxf(r.y, 0.0f);
        r.z = fmaxf(r.z, 0.0f); r.w = fmaxf(r.w, 0.0f);
    }
    __half2 a = __floats2half2_rn(r.x, r.y);
    __half2 b = __floats2half2_rn(r.z, r.w);
    *(uint2*)(out + (size_t)row * 512 + tid * 4) = make_uint2(*(uint32_t*)&a, *(uint32_t*)&b);
}

// ---------------- position embedding ----------------
__global__ void coef0_kernel(const float* __restrict__ Wp, const float* __restrict__ bp,
                             float* __restrict__ out) {
    int t = blockIdx.x;
    int e = threadIdx.x;       // 512 threads
    out[(size_t)t * EDIM + e] = (float)t * Wp[e] + bp[e];
}

// ---------------- fp16 GEMM: cp.async 3-stage + ldmatrix, 128x128x32 ---------
// C[M,N] = A[M,K] @ W[K,N] + bias ; EPI: 0 none, 1 silu, 2 decay, 3 +res
// Smem per stage: A [128 m][20 words] (16 used + 4 pad), B [32 k][68 words].
#define A_BYTES 10240               // 128*80
#define STAGE_B 18944               // A_BYTES + 32*272
#define GEMM_SMEM (3 * STAGE_B)     // 56832

template <int EPI>
__device__ __forceinline__ void gemm_load_chunk(
    const __half* __restrict__ A, const __half* __restrict__ W,
    uint32_t sbase, int st, int i, int nch, int m0, int n0, int N, int K, int tid) {
    if (i < nch) {
        int k0 = i << 5;
        uint32_t sb = sbase + st * STAGE_B;
        #pragma unroll
        for (int j = 0; j < 2; j++) {
            int idx = j * 256 + tid;          // 0..511
            int rowa = idx >> 2;              // 0..127
            int sega = idx & 3;
            uint32_t dst = sb + rowa * 80 + sega * 16;
            const __half* src = A + (size_t)(m0 + rowa) * K + k0 + sega * 8;
            CP_ASYNC16(dst, src);
        }
        #pragma unroll
        for (int j = 0; j < 2; j++) {
            int idx = j * 256 + tid;
            int rowb = idx >> 4;              // 0..31
            int nseg = idx & 15;
            uint32_t dst = sb + A_BYTES + rowb * 272 + nseg * 16;
            const __half* src = W + (size_t)(k0 + rowb) * N + n0 + nseg * 8;
            CP_ASYNC16(dst, src);
        }
    }
    CP_COMMIT();
}

template <int EPI>
__global__ void __launch_bounds__(256)
hgemm_kernel(const __half* __restrict__ A, const __half* __restrict__ W,
             const float* __restrict__ bias, const float* __restrict__ res,
             float* __restrict__ C, int M, int N, int K) {
    extern __shared__ __align__(16) uint8_t smraw[];
    uint32_t sbase = smem_u32(smraw);

    int tid = threadIdx.x;             // 256
    int n0 = blockIdx.x * 128;
    int m0 = blockIdx.y * 128;
    int warp = tid >> 5, lane = tid & 31;
    int wm = warp >> 2;                // 0..1  (64-row slab)
    int wn = warp & 3;                 // 0..3  (32-col slab)
    int g = lane >> 2, t = lane & 3;
    int l16 = lane & 15, lh = lane >> 4;

    float acc[4][4][4];
    #pragma unroll
    for (int mt = 0; mt < 4; mt++)
        #pragma unroll
        for (int nt = 0; nt < 4; nt++)
            #pragma unroll
            for (int e = 0; e < 4; e++) acc[mt][nt][e] = 0.0f;

    int nch = K >> 5;
    gemm_load_chunk<EPI>(A, W, sbase, 0, 0, nch, m0, n0, N, K, tid);
    gemm_load_chunk<EPI>(A, W, sbase, 1, 1, nch, m0, n0, N, K, tid);

    #pragma unroll 1
    for (int i = 0; i < nch; i++) {
        CP_WAIT1();
        __syncthreads();
        // issue loads for chunk i+2 (stage being recycled was computed in i-1)
        gemm_load_chunk<EPI>(A, W, sbase, (i + 2) % 3, i + 2, nch, m0, n0, N, K, tid);

        int st = i % 3;
        uint32_t sA = sbase + st * STAGE_B;
        uint32_t sB = sA + A_BYTES;

        #pragma unroll
        for (int ks = 0; ks < 2; ks++) {
            uint32_t af[4][4], bf[4][2];
            #pragma unroll
            for (int mt = 0; mt < 4; mt++) {
                int row = wm * 64 + mt * 16 + l16;
                uint32_t addr = sA + row * 80 + (ks * 2 + lh) * 16;
                LDSM_X4(af[mt][0], af[mt][1], af[mt][2], af[mt][3], addr);
            }
            #pragma unroll
            for (int p = 0; p < 2; p++) {
                int rowb = ks * 16 + l16;
                int nseg = wn * 4 + p * 2 + lh;
                uint32_t addr = sB + rowb * 272 + nseg * 16;
                LDSM_X4T(bf[2 * p][0], bf[2 * p][1], bf[2 * p + 1][0], bf[2 * p + 1][1], addr);
            }
            #pragma unroll
            for (int mt = 0; mt < 4; mt++)
                #pragma unroll
                for (int nt = 0; nt < 4; nt++)
                    MMA_F16(acc[mt][nt], af[mt], bf[nt]);
        }
    }

    float lg = logf(GAMMA_F);
    #pragma unroll
    for (int mt = 0; mt < 4; mt++) {
        int mrow0 = m0 + wm * 64 + mt * 16 + g;
        #pragma unroll
        for (int h2 = 0; h2 < 2; h2++) {
            int m = mrow0 + 8 * h2;
            float dec = 1.0f;
            if (EPI == 2) dec = (m == 0) ? 1.0f : expf((float)m * lg);
            #pragma unroll
            for (int nt = 0; nt < 4; nt++) {
                int n = n0 + wn * 32 + nt * 8 + 2 * t;
                float v0 = acc[mt][nt][2 * h2 + 0] + bias[n];
                float v1 = acc[mt][nt][2 * h2 + 1] + bias[n + 1];
                if (EPI == 1) {
                    v0 = v0 / (1.0f + expf(-v0));
                    v1 = v1 / (1.0f + expf(-v1));
                }
                if (EPI == 2) { v0 *= dec; v1 *= dec; }
                if (EPI == 3) {
                    float2 rv = *(const float2*)(res + (size_t)m * N + n);
                    v0 += rv.x; v1 += rv.y;
                }
                *(float2*)(C + (size_t)m * N + n) = make_float2(v0, v1);
            }
        }
    }
}

// ---------------- causal depthwise Toeplitz conv + gate (packed f32x2) -------
// y_h[b,t,c] = half(u[b,t,c] * sum_{r=0}^{t} arr[r,c] * v[b,t-r,c])
#define CONV_SMEM ((64 * 64 + 192 * 64) * 4)

__global__ void __launch_bounds__(256)
conv_kernel(const float* __restrict__ v, const float* __restrict__ arr,
            const float* __restrict__ u, __half* __restrict__ yh) {
    extern __shared__ float cs[];
    float* a_s = cs;              // [64][64]
    float* v_s = cs + 64 * 64;    // [192][64]

    int b = blockIdx.z;
    int c0 = blockIdx.y * 64;
    int iblk = (gridDim.x - 1) - blockIdx.x;   // heaviest tiles first
    int t0 = iblk * 128;
    int tid = threadIdx.x;                     // 256
    int tx = tid & 15;                         // c group (4 channels)
    int ty = tid >> 4;                         // t group (8 rows)

    unsigned long long acc2[8][2];
    #pragma unroll
    for (int i = 0; i < 8; i++) { acc2[i][0] = 0ULL; acc2[i][1] = 0ULL; }

    const float* vb = v + (size_t)b * NTOK * D1;
    int nch = 2 * iblk + 2;

    for (int jb = 0; jb < nch; jb++) {
        __syncthreads();
        #pragma unroll
        for (int it = 0; it < 4; it++) {
            int idx = it * 256 + tid;
            int rq = idx >> 4;
            int cseg = idx & 15;
            float4 val = *(const float4*)(arr + (size_t)(jb * 64 + rq) * D1 + c0 + cseg * 4);
            *(float4*)(&a_s[rq * 64 + cseg * 4]) = val;
        }
        int gbase = t0 - jb * 64 - 63;
        #pragma unroll
        for (int it = 0; it < 12; it++) {
            int idx = it * 256 + tid;
            int rl = idx >> 4;
            int cseg = idx & 15;
            int gg = gbase + rl;
            float4 val = make_float4(0.0f, 0.0f, 0.0f, 0.0f);
            if (gg >= 0 && gg < NTOK)
                val = *(const float4*)(vb + (size_t)gg * D1 + c0 + cseg * 4);
            *(float4*)(&v_s[rl * 64 + cseg * 4]) = val;
        }
        __syncthreads();

        unsigned long long w2[8][2];
        #pragma unroll
        for (int i = 0; i < 8; i++) {
            ulonglong2 wv = *(const ulonglong2*)(&v_s[(63 + ty * 8 + i) * 64 + tx * 4]);
            w2[i][0] = wv.x; w2[i][1] = wv.y;
        }

        #pragma unroll 8
        for (int q = 0; q < 64; q++) {
            ulonglong2 a2 = *(const ulonglong2*)(&a_s[q * 64 + tx * 4]);
            #pragma unroll
            for (int i = 0; i < 8; i++) {
                FFMA2(acc2[i][0], a2.x, w2[i][0], acc2[i][0]);
                FFMA2(acc2[i][1], a2.y, w2[i][1], acc2[i][1]);
            }
            if (q < 63) {
                #pragma unroll
                for (int i = 7; i > 0; i--) { w2[i][0] = w2[i - 1][0]; w2[i][1] = w2[i - 1][1]; }
                ulonglong2 wv = *(const ulonglong2*)(&v_s[(62 + ty * 8 - q) * 64 + tx * 4]);
                w2[0][0] = wv.x; w2[0][1] = wv.y;
            }
        }
    }

    #pragma unroll
    for (int i = 0; i < 8; i++) {
        int t = t0 + ty * 8 + i;
        size_t off = ((size_t)b * NTOK + t) * D1 + c0 + tx * 4;
        float4 uv = *(const float4*)(u + off);
        float2 lo = *(float2*)(&acc2[i][0]);
        float2 hi = *(float2*)(&acc2[i][1]);
        __half2 ha = __floats2half2_rn(uv.x * lo.x, uv.y * lo.y);
        __half2 hb = __floats2half2_rn(uv.z * hi.x, uv.w * hi.y);
        *(uint2*)(yh + off) = make_uint2(*(uint32_t*)&ha, *(uint32_t*)&hb);
    }
}

// ---------------- launch ----------------
extern "C" void kernel_launch(void* const* d_in, const int* in_sizes, int n_in,
                              void* d_out, int out_size) {
    const float* x  = (const float*)d_in[0];
    const float* Wu = (const float*)d_in[1];
    const float* bu = (const float*)d_in[2];
    const float* Wv = (const float*)d_in[3];
    const float* bv = (const float*)d_in[4];
    const float* Wo = (const float*)d_in[5];
    const float* bo = (const float*)d_in[6];
    const float* Wp = (const float*)d_in[7];
    const float* bp = (const float*)d_in[8];
    const float* W1 = (const float*)d_in[9];
    const float* b1 = (const float*)d_in[10];
    const float* W2 = (const float*)d_in[11];
    const float* b2 = (const float*)d_in[12];
    const float* W3 = (const float*)d_in[13];
    const float* b3 = (const float*)d_in[14];
    const float* Wz = (const float*)d_in[15];
    const float* bz = (const float*)d_in[16];
    float* out = (float*)d_out;

    float *u, *v, *arr, *h;
    __half *xnh, *acth, *yh, *Wuh, *Wvh, *Woh, *W1h, *W2h, *W3h, *Wzh;
    cudaGetSymbolAddress((void**)&u,    g_u);
    cudaGetSymbolAddress((void**)&v,    g_v);
    cudaGetSymbolAddress((void**)&arr,  g_arr);
    cudaGetSymbolAddress((void**)&h,    g_h);
    cudaGetSymbolAddress((void**)&xnh,  g_xnh);
    cudaGetSymbolAddress((void**)&acth, g_acth);
    cudaGetSymbolAddress((void**)&yh,   g_yh);
    cudaGetSymbolAddress((void**)&Wuh,  g_Wuh);
    cudaGetSymbolAddress((void**)&Wvh,  g_Wvh);
    cudaGetSymbolAddress((void**)&Woh,  g_Woh);
    cudaGetSymbolAddress((void**)&W1h,  g_W1h);
    cudaGetSymbolAddress((void**)&W2h,  g_W2h);
    cudaGetSymbolAddress((void**)&W3h,  g_W3h);
    cudaGetSymbolAddress((void**)&Wzh,  g_Wzh);

    cudaFuncSetAttribute(hgemm_kernel<0>, cudaFuncAttributeMaxDynamicSharedMemorySize, GEMM_SMEM);
    cudaFuncSetAttribute(hgemm_kernel<1>, cudaFuncAttributeMaxDynamicSharedMemorySize, GEMM_SMEM);
    cudaFuncSetAttribute(hgemm_kernel<2>, cudaFuncAttributeMaxDynamicSharedMemorySize, GEMM_SMEM);
    cudaFuncSetAttribute(hgemm_kernel<3>, cudaFuncAttributeMaxDynamicSharedMemorySize, GEMM_SMEM);
    cudaFuncSetAttribute(conv_kernel,     cudaFuncAttributeMaxDynamicSharedMemorySize, CONV_SMEM);

    // weight conversions (cheap, overlappable elementwise passes)
    f2h_kernel<<<(DDIM * D1 / 4 + 255) / 256, 256>>>(Wu, Wuh, DDIM * D1);
    f2h_kernel<<<(DDIM * D1 / 4 + 255) / 256, 256>>>(Wv, Wvh, DDIM * D1);
    f2h_kernel<<<(D1 * DDIM / 4 + 255) / 256, 256>>>(Wo, Woh, D1 * DDIM);
    f2h_kernel<<<(EDIM * EDIM / 4 + 255) / 256, 256>>>(W1, W1h, EDIM * EDIM);
    f2h_kernel<<<(EDIM * EDIM / 4 + 255) / 256, 256>>>(W2, W2h, EDIM * EDIM);
    f2h_kernel<<<(EDIM * EDIM / 4 + 255) / 256, 256>>>(W3, W3h, EDIM * EDIM);
    f2h_kernel<<<(EDIM * D1 / 4 + 255) / 256, 256>>>(Wz, Wzh, EDIM * D1);

    // main path norm -> fp16
    srms_kernel<false><<<ROWS, 128>>>(x, xnh);

    // u, v projections with SiLU
    hgemm_kernel<1><<<dim3(D1 / 128, ROWS / 128), 256, GEMM_SMEM>>>(xnh, Wuh, bu, nullptr, u, ROWS, D1, DDIM);
    hgemm_kernel<1><<<dim3(D1 / 128, ROWS / 128), 256, GEMM_SMEM>>>(xnh, Wvh, bv, nullptr, v, ROWS, D1, DDIM);

    // coefficient MLP (position-only)
    coef0_kernel<<<NTOK, EDIM>>>(Wp, bp, h);
    srms_kernel<true><<<NTOK, 128>>>(h, acth);
    hgemm_kernel<0><<<dim3(EDIM / 128, NTOK / 128), 256, GEMM_SMEM>>>(acth, W1h, b1, nullptr, h, NTOK, EDIM, EDIM);
    srms_kernel<true><<<NTOK, 128>>>(h, acth);
    hgemm_kernel<0><<<dim3(EDIM / 128, NTOK / 128), 256, GEMM_SMEM>>>(acth, W2h, b2, nullptr, h, NTOK, EDIM, EDIM);
    srms_kernel<true><<<NTOK, 128>>>(h, acth);
    hgemm_kernel<0><<<dim3(EDIM / 128, NTOK / 128), 256, GEMM_SMEM>>>(acth, W3h, b3, nullptr, h, NTOK, EDIM, EDIM);
    srms_kernel<true><<<NTOK, 128>>>(h, acth);
    // final coef layer with decay applied in epilogue -> arr[r, c]
    hgemm_kernel<2><<<dim3(D1 / 128, NTOK / 128), 256, GEMM_SMEM>>>(acth, Wzh, bz, nullptr, arr, NTOK, D1, EDIM);

    // causal depthwise Toeplitz conv, gated by u -> fp16 y
    conv_kernel<<<dim3(NTOK / 128, D1 / 64, NB), 256, CONV_SMEM>>>(v, arr, u, yh);

    // output projection + bias + residual
    hgemm_kernel<3><<<dim3(DDIM / 128, ROWS / 128), 256, GEMM_SMEM>>>(yh, Woh, bo, x, out, ROWS, DDIM, D1);
}

// round 11
// speedup vs baseline: 1.4139x; 1.0236x over previous
#include <cuda_runtime.h>
#include <cuda_fp16.h>
#include <math.h>
#include <stdint.h>

#define NTOK 2048
#define NB 4
#define DDIM 512
#define D1 1024
#define EDIM 512
#define ROWS (NB * NTOK)   // 8192
#define GAMMA_F 0.999f

// ---------------- scratch (device globals: allocation-free) ----------------
__device__ float  g_u  [ROWS * D1];
__device__ float  g_v  [ROWS * D1];
__device__ float  g_arr[NTOK * D1];
__device__ __half g_xnh [ROWS * DDIM];
__device__ __half g_yh  [ROWS * D1];
__device__ __half g_Wuh[DDIM * D1];
__device__ __half g_Wvh[DDIM * D1];
__device__ __half g_Woh[D1 * DDIM];
__device__ __half g_W1h[EDIM * EDIM];
__device__ __half g_W2h[EDIM * EDIM];
__device__ __half g_W3h[EDIM * EDIM];
__device__ __half g_Wzh[EDIM * D1];

// ---------------- helpers ----------------
__device__ __forceinline__ uint32_t smem_u32(const void* p) {
    uint32_t a;
    asm("{ .reg .u64 t; cvta.to.shared.u64 t, %1; cvt.u32.u64 %0, t; }" : "=r"(a) : "l"(p));
    return a;
}

#define MMA_F16(ACC, AF, BF)                                                   \
    asm volatile(                                                              \
        "mma.sync.aligned.m16n8k16.row.col.f32.f16.f16.f32 "                   \
        "{%0,%1,%2,%3}, {%4,%5,%6,%7}, {%8,%9}, {%0,%1,%2,%3};"               \
        : "+f"((ACC)[0]), "+f"((ACC)[1]), "+f"((ACC)[2]), "+f"((ACC)[3])       \
        : "r"((AF)[0]), "r"((AF)[1]), "r"((AF)[2]), "r"((AF)[3]),              \
          "r"((BF)[0]), "r"((BF)[1]))

#define LDSM_X4(R0, R1, R2, R3, A)                                             \
    asm volatile("ldmatrix.sync.aligned.m8n8.x4.shared.b16 {%0,%1,%2,%3}, [%4];" \
        : "=r"(R0), "=r"(R1), "=r"(R2), "=r"(R3) : "r"(A))

#define LDSM_X4T(R0, R1, R2, R3, A)                                            \
    asm volatile("ldmatrix.sync.aligned.m8n8.x4.trans.shared.b16 {%0,%1,%2,%3}, [%4];" \
        : "=r"(R0), "=r"(R1), "=r"(R2), "=r"(R3) : "r"(A))

#define CP_ASYNC16(DST, SRC)                                                   \
    asm volatile("cp.async.cg.shared.global [%0], [%1], 16;" :: "r"(DST), "l"(SRC))
#define CP_COMMIT() asm volatile("cp.async.commit_group;" ::: "memory")
#define CP_WAIT1()  asm volatile("cp.async.wait_group 1;" ::: "memory")

#define FFMA2(D, A, B, C)                                                      \
    asm("fma.rn.f32x2 %0, %1, %2, %3;" : "=l"(D) : "l"(A), "l"(B), "l"(C))

// ---------------- one-shot fp32->fp16 conversion of all 7 weights -----------
__global__ void f2h_all_kernel(const float* __restrict__ Wu, const float* __restrict__ Wv,
                               const float* __restrict__ Wo, const float* __restrict__ W1,
                               const float* __restrict__ W2, const float* __restrict__ W3,
                               const float* __restrict__ Wz,
                               __half* ou, __half* ov, __half* oo,
                               __half* o1, __half* o2, __half* o3, __half* oz) {
    int i = blockIdx.x * 256 + threadIdx.x;    // float4 index
    const float* src; __half* dst; int off;
    if      (i < 131072) { src = Wu; dst = ou; off = i; }
    else if (i < 262144) { src = Wv; dst = ov; off = i - 131072; }
    else if (i < 393216) { src = Wo; dst = oo; off = i - 262144; }
    else if (i < 458752) { src = W1; dst = o1; off = i - 393216; }
    else if (i < 524288) { src = W2; dst = o2; off = i - 458752; }
    else if (i < 589824) { src = W3; dst = o3; off = i - 524288; }
    else if (i < 720896) { src = Wz; dst = oz; off = i - 589824; }
    else return;
    float4 vv = *(const float4*)(src + off * 4);
    __half2 a = __floats2half2_rn(vv.x, vv.y);
    __half2 b = __floats2half2_rn(vv.z, vv.w);
    *(uint2*)(dst + off * 4) = make_uint2(*(uint32_t*)&a, *(uint32_t*)&b);
}

// ---------------- sRMS norm, dim = 512, fp16 out ----------------
__global__ void srms_kernel(const float* __restrict__ in, __half* __restrict__ out) {
    int row = blockIdx.x;
    const float4* ip = (const float4*)(in + (size_t)row * 512);
    int tid = threadIdx.x;                    // 0..127
    float4 val = ip[tid];
    float ss = val.x * val.x + val.y * val.y + val.z * val.z + val.w * val.w;
    #pragma unroll
    for (int o = 16; o > 0; o >>= 1) ss += __shfl_xor_sync(0xffffffffu, ss, o);
    __shared__ float wsum[4];
    if ((tid & 31) == 0) wsum[tid >> 5] = ss;
    __syncthreads();
    float tot = wsum[0] + wsum[1] + wsum[2] + wsum[3];
    float inv = 1.0f / (sqrtf(tot * (1.0f / 512.0f)) + 1e-8f);
    __half2 a = __floats2half2_rn(val.x * inv, val.y * inv);
    __half2 b = __floats2half2_rn(val.z * inv, val.w * inv);
    *(uint2*)(out + (size_t)row * 512 + tid * 4) = make_uint2(*(uint32_t*)&a, *(uint32_t*)&b);
}

// ---------------- fused coefficient MLP -------------------------------------
// One block = 16 positions. Full chain:
//   h0 = t*Wp + bp ; act = relu(srms(h0))
//   3x: act = relu(srms(act @ W + b))
//   arr = decay(r) * (act @ Wz + bz)
// GEMMs are 16x512xK fp16 MMA; weights streamed via cp.async (3 stages).
#define CSTR 520                       // halfs per act/Bs row (512 + 8 pad)
#define CROWB (CSTR * 2)               // 1040 bytes
#define ACT_B (16 * CROWB)             // 16640
#define BSTG (32 * CROWB)              // 33280
#define COEF_SMEM (2 * ACT_B + 3 * BSTG + 1024)   // 134144

__device__ __forceinline__ void coef_load(const __half* __restrict__ Wg, int Nfull,
                                          int cOff, uint32_t bsBase, int st, int chunk,
                                          int tid) {
    if (chunk < 16) {
        uint32_t sb = bsBase + st * BSTG;
        int k0 = chunk * 32;
        #pragma unroll
        for (int j = 0; j < 8; j++) {
            int idx = j * 256 + tid;        // 0..2047
            int row = idx >> 6;             // 0..31
            int seg = idx & 63;             // 16B segments
            uint32_t dst = sb + row * CROWB + seg * 16;
            const __half* src = Wg + (size_t)(k0 + row) * Nfull + cOff + seg * 8;
            CP_ASYNC16(dst, src);
        }
    }
    CP_COMMIT();
}

// 16x512xK GEMM: acc[nt][e] over warp n-slab of 64 cols
__device__ __forceinline__ void coef_gemm(uint32_t actAddr, const __half* __restrict__ Wg,
                                          int Nfull, int cOff, uint32_t bsBase,
                                          float acc[8][4], int tid, int warp,
                                          int l16, int lh) {
    coef_load(Wg, Nfull, cOff, bsBase, 0, 0, tid);
    coef_load(Wg, Nfull, cOff, bsBase, 1, 1, tid);
    #pragma unroll 1
    for (int i = 0; i < 16; i++) {
        CP_WAIT1();
        __syncthreads();
        coef_load(Wg, Nfull, cOff, bsBase, (i + 2) % 3, i + 2, tid);
        uint32_t sB = bsBase + (i % 3) * BSTG;
        #pragma unroll
        for (int ks = 0; ks < 2; ks++) {
            uint32_t af[4];
            LDSM_X4(af[0], af[1], af[2], af[3],
                    actAddr + l16 * CROWB + i * 64 + ks * 32 + lh * 16);
            uint32_t bf[8][2];
            #pragma unroll
            for (int p = 0; p < 4; p++) {
                uint32_t baddr = sB + (ks * 16 + l16) * CROWB + warp * 128 + p * 32 + lh * 16;
                LDSM_X4T(bf[2 * p][0], bf[2 * p][1], bf[2 * p + 1][0], bf[2 * p + 1][1], baddr);
            }
            #pragma unroll
            for (int nt = 0; nt < 8; nt++) MMA_F16(acc[nt], af, bf[nt]);
        }
    }
}

__global__ void __launch_bounds__(256)
coef_mlp_kernel(const float* __restrict__ Wp, const float* __restrict__ bp,
                const __half* __restrict__ W1h, const float* __restrict__ b1,
                const __half* __restrict__ W2h, const float* __restrict__ b2,
                const __half* __restrict__ W3h, const float* __restrict__ b3,
                const __half* __restrict__ Wzh, const float* __restrict__ bz,
                float* __restrict__ arr) {
    extern __shared__ __align__(16) uint8_t sm[];
    __half* actA = (__half*)sm;
    __half* actB = (__half*)(sm + ACT_B);
    uint32_t bsBase = smem_u32(sm) + 2 * ACT_B;
    float* red = (float*)(sm + 2 * ACT_B + 3 * BSTG);    // [16][8]

    int tid = threadIdx.x, warp = tid >> 5, lane = tid & 31;
    int l16 = lane & 15, lh = lane >> 4;
    int g = lane >> 2, t4 = lane & 3;
    int t0 = blockIdx.x * 16;
    float lg = logf(GAMMA_F);

    // ---- act0 = relu(srms(t*Wp + bp)) ----
    {
        int r = tid >> 4;                  // 0..15
        int c0 = (tid & 15) * 32;
        float tv = (float)(t0 + r);
        float vals[32];
        float ss = 0.0f;
        #pragma unroll
        for (int j = 0; j < 32; j++) {
            float hv = tv * Wp[c0 + j] + bp[c0 + j];
            vals[j] = hv;
            ss += hv * hv;
        }
        #pragma unroll
        for (int o = 8; o > 0; o >>= 1) ss += __shfl_xor_sync(0xffffffffu, ss, o);
        float inv = 1.0f / (sqrtf(ss * (1.0f / 512.0f)) + 1e-8f);
        __half* dst = actA + r * CSTR + c0;
        #pragma unroll
        for (int j = 0; j < 32; j += 2) {
            __half2 h = __floats2half2_rn(fmaxf(vals[j] * inv, 0.0f),
                                          fmaxf(vals[j + 1] * inv, 0.0f));
            *(uint32_t*)(dst + j) = *(uint32_t*)&h;
        }
    }
    __syncthreads();

    __half* cur = actA;
    __half* nxt = actB;

    // ---- three hidden layers ----
    #pragma unroll 1
    for (int layer = 0; layer < 3; layer++) {
        const __half* Wg = (layer == 0) ? W1h : (layer == 1) ? W2h : W3h;
        const float* bg  = (layer == 0) ? b1  : (layer == 1) ? b2  : b3;
        float acc[8][4];
        #pragma unroll
        for (int nt = 0; nt < 8; nt++)
            #pragma unroll
            for (int e = 0; e < 4; e++) acc[nt][e] = 0.0f;

        coef_gemm(smem_u32(cur), Wg, 512, 0, bsBase, acc, tid, warp, l16, lh);

        // epilogue: +bias, srms over 512 cols (cross-warp), relu, -> nxt (fp16)
        float ssA = 0.0f, ssB = 0.0f;
        #pragma unroll
        for (int nt = 0; nt < 8; nt++) {
            float2 bv = *(const float2*)(bg + warp * 64 + nt * 8 + 2 * t4);
            acc[nt][0] += bv.x; acc[nt][1] += bv.y;
            acc[nt][2] += bv.x; acc[nt][3] += bv.y;
            ssA += acc[nt][0] * acc[nt][0] + acc[nt][1] * acc[nt][1];
            ssB += acc[nt][2] * acc[nt][2] + acc[nt][3] * acc[nt][3];
        }
        ssA += __shfl_xor_sync(0xffffffffu, ssA, 1);
        ssA += __shfl_xor_sync(0xffffffffu, ssA, 2);
        ssB += __shfl_xor_sync(0xffffffffu, ssB, 1);
        ssB += __shfl_xor_sync(0xffffffffu, ssB, 2);
        __syncthreads();                 // Bs no longer needed; reuse barrier for red
        if (t4 == 0) {
            red[g * 8 + warp] = ssA;
            red[(g + 8) * 8 + warp] = ssB;
        }
        __syncthreads();
        float totA = 0.0f, totB = 0.0f;
        #pragma unroll
        for (int w2 = 0; w2 < 8; w2++) { totA += red[g * 8 + w2]; totB += red[(g + 8) * 8 + w2]; }
        float invA = 1.0f / (sqrtf(totA * (1.0f / 512.0f)) + 1e-8f);
        float invB = 1.0f / (sqrtf(totB * (1.0f / 512.0f)) + 1e-8f);
        #pragma unroll
        for (int nt = 0; nt < 8; nt++) {
            int col = warp * 64 + nt * 8 + 2 * t4;
            __half2 ha = __floats2half2_rn(fmaxf(acc[nt][0] * invA, 0.0f),
                                           fmaxf(acc[nt][1] * invA, 0.0f));
            __half2 hb = __floats2half2_rn(fmaxf(acc[nt][2] * invB, 0.0f),
                                           fmaxf(acc[nt][3] * invB, 0.0f));
            *(uint32_t*)(nxt + g * CSTR + col) = *(uint32_t*)&ha;
            *(uint32_t*)(nxt + (g + 8) * CSTR + col) = *(uint32_t*)&hb;
        }
        __syncthreads();
        __half* tmp = cur; cur = nxt; nxt = tmp;
    }

    // ---- final layer (Wz, N=1024): two 512-col passes + decay -> arr -------
    int rA = t0 + g, rB = t0 + g + 8;
    float decA = (rA == 0) ? 1.0f : expf((float)rA * lg);
    float decB = expf((float)rB * lg);
    #pragma unroll 1
    for (int nb = 0; nb < 2; nb++) {
        float acc[8][4];
        #pragma unroll
        for (int nt = 0; nt < 8; nt++)
            #pragma unroll
            for (int e = 0; e < 4; e++) acc[nt][e] = 0.0f;

        coef_gemm(smem_u32(cur), Wzh, 1024, nb * 512, bsBase, acc, tid, warp, l16, lh);

        #pragma unroll
        for (int nt = 0; nt < 8; nt++) {
            int col = nb * 512 + warp * 64 + nt * 8 + 2 * t4;
            float2 bv = *(const float2*)(bz + col);
            float2 oa = make_float2(decA * (acc[nt][0] + bv.x), decA * (acc[nt][1] + bv.y));
            float2 ob = make_float2(decB * (acc[nt][2] + bv.x), decB * (acc[nt][3] + bv.y));
            *(float2*)(arr + (size_t)rA * D1 + col) = oa;
            *(float2*)(arr + (size_t)rB * D1 + col) = ob;
        }
        __syncthreads();                 // before next pass overwrites Bs
    }
}

// ---------------- fp16 GEMM: cp.async 3-stage + ldmatrix, 128x128x32 ---------
// C[M,N] = A[M,K] @ W[K,N] + bias ; EPI: 1 silu, 3 +res
#define A_BYTES 10240               // 128*80
#define STAGE_B 18944               // A_BYTES + 32*272
#define GEMM_SMEM (3 * STAGE_B)     // 56832

template <int EPI>
__device__ __forceinline__ void gemm_load_chunk(
    const __half* __restrict__ A, const __half* __restrict__ W,
    uint32_t sbase, int st, int i, int nch, int m0, int n0, int N, int K, int tid) {
    if (i < nch) {
        int k0 = i << 5;
        uint32_t sb = sbase + st * STAGE_B;
        #pragma unroll
        for (int j = 0; j < 2; j++) {
            int idx = j * 256 + tid;          // 0..511
            int rowa = idx >> 2;              // 0..127
            int sega = idx & 3;
            uint32_t dst = sb + rowa * 80 + sega * 16;
            const __half* src = A + (size_t)(m0 + rowa) * K + k0 + sega * 8;
            CP_ASYNC16(dst, src);
        }
        #pragma unroll
        for (int j = 0; j < 2; j++) {
            int idx = j * 256 + tid;
            int rowb = idx >> 4;              // 0..31
            int nseg = idx & 15;
            uint32_t dst = sb + A_BYTES + rowb * 272 + nseg * 16;
            const __half* src = W + (size_t)(k0 + rowb) * N + n0 + nseg * 8;
            CP_ASYNC16(dst, src);
        }
    }
    CP_COMMIT();
}

template <int EPI>
__global__ void __launch_bounds__(256)
hgemm_kernel(const __half* __restrict__ A, const __half* __restrict__ W,
             const float* __restrict__ bias, const float* __restrict__ res,
             float* __restrict__ C, int M, int N, int K) {
    extern __shared__ __align__(16) uint8_t smraw[];
    uint32_t sbase = smem_u32(smraw);

    int tid = threadIdx.x;             // 256
    int n0 = blockIdx.x * 128;
    int m0 = blockIdx.y * 128;
    int warp = tid >> 5, lane = tid & 31;
    int wm = warp >> 2;                // 0..1  (64-row slab)
    int wn = warp & 3;                 // 0..3  (32-col slab)
    int g = lane >> 2, t = lane & 3;
    int l16 = lane & 15, lh = lane >> 4;

    float acc[4][4][4];
    #pragma unroll
    for (int mt = 0; mt < 4; mt++)
        #pragma unroll
        for (int nt = 0; nt < 4; nt++)
            #pragma unroll
            for (int e = 0; e < 4; e++) acc[mt][nt][e] = 0.0f;

    int nch = K >> 5;
    gemm_load_chunk<EPI>(A, W, sbase, 0, 0, nch, m0, n0, N, K, tid);
    gemm_load_chunk<EPI>(A, W, sbase, 1, 1, nch, m0, n0, N, K, tid);

    #pragma unroll 1
    for (int i = 0; i < nch; i++) {
        CP_WAIT1();
        __syncthreads();
        gemm_load_chunk<EPI>(A, W, sbase, (i + 2) % 3, i + 2, nch, m0, n0, N, K, tid);

        int st = i % 3;
        uint32_t sA = sbase + st * STAGE_B;
        uint32_t sB = sA + A_BYTES;

        #pragma unroll
        for (int ks = 0; ks < 2; ks++) {
            uint32_t af[4][4], bf[4][2];
            #pragma unroll
            for (int mt = 0; mt < 4; mt++) {
                int row = wm * 64 + mt * 16 + l16;
                uint32_t addr = sA + row * 80 + (ks * 2 + lh) * 16;
                LDSM_X4(af[mt][0], af[mt][1], af[mt][2], af[mt][3], addr);
            }
            #pragma unroll
            for (int p = 0; p < 2; p++) {
                int rowb = ks * 16 + l16;
                int nseg = wn * 4 + p * 2 + lh;
                uint32_t addr = sB + rowb * 272 + nseg * 16;
                LDSM_X4T(bf[2 * p][0], bf[2 * p][1], bf[2 * p + 1][0], bf[2 * p + 1][1], addr);
            }
            #pragma unroll
            for (int mt = 0; mt < 4; mt++)
                #pragma unroll
                for (int nt = 0; nt < 4; nt++)
                    MMA_F16(acc[mt][nt], af[mt], bf[nt]);
        }
    }

    #pragma unroll
    for (int mt = 0; mt < 4; mt++) {
        int mrow0 = m0 + wm * 64 + mt * 16 + g;
        #pragma unroll
        for (int h2 = 0; h2 < 2; h2++) {
            int m = mrow0 + 8 * h2;
            #pragma unroll
            for (int nt = 0; nt < 4; nt++) {
                int n = n0 + wn * 32 + nt * 8 + 2 * t;
                float v0 = acc[mt][nt][2 * h2 + 0] + bias[n];
                float v1 = acc[mt][nt][2 * h2 + 1] + bias[n + 1];
                if (EPI == 1) {
                    v0 = v0 / (1.0f + expf(-v0));
                    v1 = v1 / (1.0f + expf(-v1));
                }
                if (EPI == 3) {
                    float2 rv = *(const float2*)(res + (size_t)m * N + n);
                    v0 += rv.x; v1 += rv.y;
                }
                *(float2*)(C + (size_t)m * N + n) = make_float2(v0, v1);
            }
        }
    }
}

// ---------------- causal depthwise Toeplitz conv + gate (packed f32x2) -------
#define CONV_SMEM ((64 * 64 + 192 * 64) * 4)

__global__ void __launch_bounds__(256)
conv_kernel(const float* __restrict__ v, const float* __restrict__ arr,
            const float* __restrict__ u, __half* __restrict__ yh) {
    extern __shared__ float cs[];
    float* a_s = cs;              // [64][64]
    float* v_s = cs + 64 * 64;    // [192][64]

    int b = blockIdx.z;
    int c0 = blockIdx.y * 64;
    int iblk = (gridDim.x - 1) - blockIdx.x;   // heaviest tiles first
    int t0 = iblk * 128;
    int tid = threadIdx.x;                     // 256
    int tx = tid & 15;                         // c group (4 channels)
    int ty = tid >> 4;                         // t group (8 rows)

    unsigned long long acc2[8][2];
    #pragma unroll
    for (int i = 0; i < 8; i++) { acc2[i][0] = 0ULL; acc2[i][1] = 0ULL; }

    const float* vb = v + (size_t)b * NTOK * D1;
    int nch = 2 * iblk + 2;

    for (int jb = 0; jb < nch; jb++) {
        __syncthreads();
        #pragma unroll
        for (int it = 0; it < 4; it++) {
            int idx = it * 256 + tid;
            int rq = idx >> 4;
            int cseg = idx & 15;
            float4 val = *(const float4*)(arr + (size_t)(jb * 64 + rq) * D1 + c0 + cseg * 4);
            *(float4*)(&a_s[rq * 64 + cseg * 4]) = val;
        }
        int gbase = t0 - jb * 64 - 63;
        #pragma unroll
        for (int it = 0; it < 12; it++) {
            int idx = it * 256 + tid;
            int rl = idx >> 4;
            int cseg = idx & 15;
            int gg = gbase + rl;
            float4 val = make_float4(0.0f, 0.0f, 0.0f, 0.0f);
            if (gg >= 0 && gg < NTOK)
                val = *(const float4*)(vb + (size_t)gg * D1 + c0 + cseg * 4);
            *(float4*)(&v_s[rl * 64 + cseg * 4]) = val;
        }
        __syncthreads();

        unsigned long long w2[8][2];
        #pragma unroll
        for (int i = 0; i < 8; i++) {
            ulonglong2 wv = *(const ulonglong2*)(&v_s[(63 + ty * 8 + i) * 64 + tx * 4]);
            w2[i][0] = wv.x; w2[i][1] = wv.y;
        }

        #pragma unroll 8
        for (int q = 0; q < 64; q++) {
            ulonglong2 a2 = *(const ulonglong2*)(&a_s[q * 64 + tx * 4]);
            #pragma unroll
            for (int i = 0; i < 8; i++) {
                FFMA2(acc2[i][0], a2.x, w2[i][0], acc2[i][0]);
                FFMA2(acc2[i][1], a2.y, w2[i][1], acc2[i][1]);
            }
            if (q < 63) {
                #pragma unroll
                for (int i = 7; i > 0; i--) { w2[i][0] = w2[i - 1][0]; w2[i][1] = w2[i - 1][1]; }
                ulonglong2 wv = *(const ulonglong2*)(&v_s[(62 + ty * 8 - q) * 64 + tx * 4]);
                w2[0][0] = wv.x; w2[0][1] = wv.y;
            }
        }
    }

    #pragma unroll
    for (int i = 0; i < 8; i++) {
        int t = t0 + ty * 8 + i;
        size_t off = ((size_t)b * NTOK + t) * D1 + c0 + tx * 4;
        float4 uv = *(const float4*)(u + off);
        float2 lo = *(float2*)(&acc2[i][0]);
        float2 hi = *(float2*)(&acc2[i][1]);
        __half2 ha = __floats2half2_rn(uv.x * lo.x, uv.y * lo.y);
        __half2 hb = __floats2half2_rn(uv.z * hi.x, uv.w * hi.y);
        *(uint2*)(yh + off) = make_uint2(*(uint32_t*)&ha, *(uint32_t*)&hb);
    }
}

// ---------------- launch ----------------
extern "C" void kernel_launch(void* const* d_in, const int* in_sizes, int n_in,
                              void* d_out, int out_size) {
    const float* x  = (const float*)d_in[0];
    const float* Wu = (const float*)d_in[1];
    const float* bu = (const float*)d_in[2];
    const float* Wv = (const float*)d_in[3];
    const float* bv = (const float*)d_in[4];
    const float* Wo = (const float*)d_in[5];
    const float* bo = (const float*)d_in[6];
    const float* Wp = (const float*)d_in[7];
    const float* bp = (const float*)d_in[8];
    const float* W1 = (const float*)d_in[9];
    const float* b1 = (const float*)d_in[10];
    const float* W2 = (const float*)d_in[11];
    const float* b2 = (const float*)d_in[12];
    const float* W3 = (const float*)d_in[13];
    const float* b3 = (const float*)d_in[14];
    const float* Wz = (const float*)d_in[15];
    const float* bz = (const float*)d_in[16];
    float* out = (float*)d_out;

    float *u, *v, *arr;
    __half *xnh, *yh, *Wuh, *Wvh, *Woh, *W1h, *W2h, *W3h, *Wzh;
    cudaGetSymbolAddress((void**)&u,    g_u);
    cudaGetSymbolAddress((void**)&v,    g_v);
    cudaGetSymbolAddress((void**)&arr,  g_arr);
    cudaGetSymbolAddress((void**)&xnh,  g_xnh);
    cudaGetSymbolAddress((void**)&yh,   g_yh);
    cudaGetSymbolAddress((void**)&Wuh,  g_Wuh);
    cudaGetSymbolAddress((void**)&Wvh,  g_Wvh);
    cudaGetSymbolAddress((void**)&Woh,  g_Woh);
    cudaGetSymbolAddress((void**)&W1h,  g_W1h);
    cudaGetSymbolAddress((void**)&W2h,  g_W2h);
    cudaGetSymbolAddress((void**)&W3h,  g_W3h);
    cudaGetSymbolAddress((void**)&Wzh,  g_Wzh);

    cudaFuncSetAttribute(hgemm_kernel<1>, cudaFuncAttributeMaxDynamicSharedMemorySize, GEMM_SMEM);
    cudaFuncSetAttribute(hgemm_kernel<3>, cudaFuncAttributeMaxDynamicSharedMemorySize, GEMM_SMEM);
    cudaFuncSetAttribute(conv_kernel,     cudaFuncAttributeMaxDynamicSharedMemorySize, CONV_SMEM);
    cudaFuncSetAttribute(coef_mlp_kernel, cudaFuncAttributeMaxDynamicSharedMemorySize, COEF_SMEM);

    // all weight conversions in one launch
    f2h_all_kernel<<<2816, 256>>>(Wu, Wv, Wo, W1, W2, W3, Wz,
                                  Wuh, Wvh, Woh, W1h, W2h, W3h, Wzh);

    // main path norm -> fp16
    srms_kernel<<<ROWS, 128>>>(x, xnh);

    // fused position-coefficient MLP -> arr (with decay)
    coef_mlp_kernel<<<NTOK / 16, 256, COEF_SMEM>>>(Wp, bp, W1h, b1, W2h, b2,
                                                   W3h, b3, Wzh, bz, arr);

    // u, v projections with SiLU
    hgemm_kernel<1><<<dim3(D1 / 128, ROWS / 128), 256, GEMM_SMEM>>>(xnh, Wuh, bu, nullptr, u, ROWS, D1, DDIM);
    hgemm_kernel<1><<<dim3(D1 / 128, ROWS / 128), 256, GEMM_SMEM>>>(xnh, Wvh, bv, nullptr, v, ROWS, D1, DDIM);

    // causal depthwise Toeplitz conv, gated by u -> fp16 y
    conv_kernel<<<dim3(NTOK / 128, D1 / 64, NB), 256, CONV_SMEM>>>(v, arr, u, yh);

    // output projection + bias + residual
    hgemm_kernel<3><<<dim3(DDIM / 128, ROWS / 128), 256, GEMM_SMEM>>>(yh, Woh, bo, x, out, ROWS, DDIM, D1);
}

// round 12
// speedup vs baseline: 1.4591x; 1.0319x over previous
#include <cuda_runtime.h>
#include <cuda_fp16.h>
#include <math.h>
#include <stdint.h>

#define NTOK 2048
#define NB 4
#define DDIM 512
#define D1 1024
#define EDIM 512
#define ROWS (NB * NTOK)   // 8192
#define GAMMA_F 0.999f

// ---------------- scratch (device globals: allocation-free) ----------------
__device__ float  g_u  [ROWS * D1];
__device__ float  g_v  [ROWS * D1];
__device__ float  g_arr[NTOK * D1];
__device__ __half g_xnh [ROWS * DDIM];
__device__ __half g_yh  [ROWS * D1];
__device__ __half g_Wuh[DDIM * D1];
__device__ __half g_Wvh[DDIM * D1];
__device__ __half g_Woh[D1 * DDIM];
__device__ __half g_W1h[EDIM * EDIM];
__device__ __half g_W2h[EDIM * EDIM];
__device__ __half g_W3h[EDIM * EDIM];
__device__ __half g_Wzh[EDIM * D1];

// ---------------- helpers ----------------
__device__ __forceinline__ uint32_t smem_u32(const void* p) {
    uint32_t a;
    asm("{ .reg .u64 t; cvta.to.shared.u64 t, %1; cvt.u32.u64 %0, t; }" : "=r"(a) : "l"(p));
    return a;
}

#define MMA_F16(ACC, AF, BF)                                                   \
    asm volatile(                                                              \
        "mma.sync.aligned.m16n8k16.row.col.f32.f16.f16.f32 "                   \
        "{%0,%1,%2,%3}, {%4,%5,%6,%7}, {%8,%9}, {%0,%1,%2,%3};"               \
        : "+f"((ACC)[0]), "+f"((ACC)[1]), "+f"((ACC)[2]), "+f"((ACC)[3])       \
        : "r"((AF)[0]), "r"((AF)[1]), "r"((AF)[2]), "r"((AF)[3]),              \
          "r"((BF)[0]), "r"((BF)[1]))

#define LDSM_X4(R0, R1, R2, R3, A)                                             \
    asm volatile("ldmatrix.sync.aligned.m8n8.x4.shared.b16 {%0,%1,%2,%3}, [%4];" \
        : "=r"(R0), "=r"(R1), "=r"(R2), "=r"(R3) : "r"(A))

#define LDSM_X4T(R0, R1, R2, R3, A)                                            \
    asm volatile("ldmatrix.sync.aligned.m8n8.x4.trans.shared.b16 {%0,%1,%2,%3}, [%4];" \
        : "=r"(R0), "=r"(R1), "=r"(R2), "=r"(R3) : "r"(A))

#define CP_ASYNC16(DST, SRC)                                                   \
    asm volatile("cp.async.cg.shared.global [%0], [%1], 16;" :: "r"(DST), "l"(SRC))
#define CP_COMMIT() asm volatile("cp.async.commit_group;" ::: "memory")
#define CP_WAIT2()  asm volatile("cp.async.wait_group 2;" ::: "memory")
#define CP_WAIT3()  asm volatile("cp.async.wait_group 3;" ::: "memory")

#define FFMA2(D, A, B, C)                                                      \
    asm("fma.rn.f32x2 %0, %1, %2, %3;" : "=l"(D) : "l"(A), "l"(B), "l"(C))

// ---------------- one-shot fp32->fp16 conversion of all 7 weights -----------
__global__ void f2h_all_kernel(const float* __restrict__ Wu, const float* __restrict__ Wv,
                               const float* __restrict__ Wo, const float* __restrict__ W1,
                               const float* __restrict__ W2, const float* __restrict__ W3,
                               const float* __restrict__ Wz,
                               __half* ou, __half* ov, __half* oo,
                               __half* o1, __half* o2, __half* o3, __half* oz) {
    int i = blockIdx.x * 256 + threadIdx.x;    // float4 index
    const float* src; __half* dst; int off;
    if      (i < 131072) { src = Wu; dst = ou; off = i; }
    else if (i < 262144) { src = Wv; dst = ov; off = i - 131072; }
    else if (i < 393216) { src = Wo; dst = oo; off = i - 262144; }
    else if (i < 458752) { src = W1; dst = o1; off = i - 393216; }
    else if (i < 524288) { src = W2; dst = o2; off = i - 458752; }
    else if (i < 589824) { src = W3; dst = o3; off = i - 524288; }
    else if (i < 720896) { src = Wz; dst = oz; off = i - 589824; }
    else return;
    float4 vv = *(const float4*)(src + off * 4);
    __half2 a = __floats2half2_rn(vv.x, vv.y);
    __half2 b = __floats2half2_rn(vv.z, vv.w);
    *(uint2*)(dst + off * 4) = make_uint2(*(uint32_t*)&a, *(uint32_t*)&b);
}

// ---------------- sRMS norm, dim = 512, fp16 out ----------------
__global__ void srms_kernel(const float* __restrict__ in, __half* __restrict__ out) {
    int row = blockIdx.x;
    const float4* ip = (const float4*)(in + (size_t)row * 512);
    int tid = threadIdx.x;                    // 0..127
    float4 val = ip[tid];
    float ss = val.x * val.x + val.y * val.y + val.z * val.z + val.w * val.w;
    #pragma unroll
    for (int o = 16; o > 0; o >>= 1) ss += __shfl_xor_sync(0xffffffffu, ss, o);
    __shared__ float wsum[4];
    if ((tid & 31) == 0) wsum[tid >> 5] = ss;
    __syncthreads();
    float tot = wsum[0] + wsum[1] + wsum[2] + wsum[3];
    float inv = 1.0f / (sqrtf(tot * (1.0f / 512.0f)) + 1e-8f);
    __half2 a = __floats2half2_rn(val.x * inv, val.y * inv);
    __half2 b = __floats2half2_rn(val.z * inv, val.w * inv);
    *(uint2*)(out + (size_t)row * 512 + tid * 4) = make_uint2(*(uint32_t*)&a, *(uint32_t*)&b);
}

// ---------------- fused coefficient MLP (4-stage cp.async) -------------------
#define CSTR 520                       // halfs per act/Bs row (512 + 8 pad)
#define CROWB (CSTR * 2)               // 1040 bytes
#define ACT_B (16 * CROWB)             // 16640
#define BSTG (32 * CROWB)              // 33280
#define COEF_STAGES 4
#define COEF_SMEM (2 * ACT_B + COEF_STAGES * BSTG + 1024)   // 167424

__device__ __forceinline__ void coef_load(const __half* __restrict__ Wg, int Nfull,
                                          int cOff, uint32_t bsBase, int st, int chunk,
                                          int tid) {
    if (chunk < 16) {
        uint32_t sb = bsBase + st * BSTG;
        int k0 = chunk * 32;
        #pragma unroll
        for (int j = 0; j < 8; j++) {
            int idx = j * 256 + tid;        // 0..2047
            int row = idx >> 6;             // 0..31
            int seg = idx & 63;             // 16B segments
            uint32_t dst = sb + row * CROWB + seg * 16;
            const __half* src = Wg + (size_t)(k0 + row) * Nfull + cOff + seg * 8;
            CP_ASYNC16(dst, src);
        }
    }
    CP_COMMIT();
}

__device__ __forceinline__ void coef_gemm(uint32_t actAddr, const __half* __restrict__ Wg,
                                          int Nfull, int cOff, uint32_t bsBase,
                                          float acc[8][4], int tid, int warp,
                                          int l16, int lh) {
    coef_load(Wg, Nfull, cOff, bsBase, 0, 0, tid);
    coef_load(Wg, Nfull, cOff, bsBase, 1, 1, tid);
    coef_load(Wg, Nfull, cOff, bsBase, 2, 2, tid);
    #pragma unroll 1
    for (int i = 0; i < 16; i++) {
        CP_WAIT2();
        __syncthreads();
        coef_load(Wg, Nfull, cOff, bsBase, (i + 3) % COEF_STAGES, i + 3, tid);
        uint32_t sB = bsBase + (i % COEF_STAGES) * BSTG;
        #pragma unroll
        for (int ks = 0; ks < 2; ks++) {
            uint32_t af[4];
            LDSM_X4(af[0], af[1], af[2], af[3],
                    actAddr + l16 * CROWB + i * 64 + ks * 32 + lh * 16);
            uint32_t bf[8][2];
            #pragma unroll
            for (int p = 0; p < 4; p++) {
                uint32_t baddr = sB + (ks * 16 + l16) * CROWB + warp * 128 + p * 32 + lh * 16;
                LDSM_X4T(bf[2 * p][0], bf[2 * p][1], bf[2 * p + 1][0], bf[2 * p + 1][1], baddr);
            }
            #pragma unroll
            for (int nt = 0; nt < 8; nt++) MMA_F16(acc[nt], af, bf[nt]);
        }
    }
}

__global__ void __launch_bounds__(256)
coef_mlp_kernel(const float* __restrict__ Wp, const float* __restrict__ bp,
                const __half* __restrict__ W1h, const float* __restrict__ b1,
                const __half* __restrict__ W2h, const float* __restrict__ b2,
                const __half* __restrict__ W3h, const float* __restrict__ b3,
                const __half* __restrict__ Wzh, const float* __restrict__ bz,
                float* __restrict__ arr) {
    extern __shared__ __align__(16) uint8_t sm[];
    __half* actA = (__half*)sm;
    __half* actB = (__half*)(sm + ACT_B);
    uint32_t bsBase = smem_u32(sm) + 2 * ACT_B;
    float* red = (float*)(sm + 2 * ACT_B + COEF_STAGES * BSTG);    // [16][8]

    int tid = threadIdx.x, warp = tid >> 5, lane = tid & 31;
    int l16 = lane & 15, lh = lane >> 4;
    int g = lane >> 2, t4 = lane & 3;
    int t0 = blockIdx.x * 16;
    float lg = logf(GAMMA_F);

    // ---- act0 = relu(srms(t*Wp + bp)) ----
    {
        int r = tid >> 4;                  // 0..15
        int c0 = (tid & 15) * 32;
        float tv = (float)(t0 + r);
        float vals[32];
        float ss = 0.0f;
        #pragma unroll
        for (int j = 0; j < 32; j++) {
            float hv = tv * Wp[c0 + j] + bp[c0 + j];
            vals[j] = hv;
            ss += hv * hv;
        }
        #pragma unroll
        for (int o = 8; o > 0; o >>= 1) ss += __shfl_xor_sync(0xffffffffu, ss, o);
        float inv = 1.0f / (sqrtf(ss * (1.0f / 512.0f)) + 1e-8f);
        __half* dst = actA + r * CSTR + c0;
        #pragma unroll
        for (int j = 0; j < 32; j += 2) {
            __half2 h = __floats2half2_rn(fmaxf(vals[j] * inv, 0.0f),
                                          fmaxf(vals[j + 1] * inv, 0.0f));
            *(uint32_t*)(dst + j) = *(uint32_t*)&h;
        }
    }
    __syncthreads();

    __half* cur = actA;
    __half* nxt = actB;

    // ---- three hidden layers ----
    #pragma unroll 1
    for (int layer = 0; layer < 3; layer++) {
        const __half* Wg = (layer == 0) ? W1h : (layer == 1) ? W2h : W3h;
        const float* bg  = (layer == 0) ? b1  : (layer == 1) ? b2  : b3;
        float acc[8][4];
        #pragma unroll
        for (int nt = 0; nt < 8; nt++)
            #pragma unroll
            for (int e = 0; e < 4; e++) acc[nt][e] = 0.0f;

        coef_gemm(smem_u32(cur), Wg, 512, 0, bsBase, acc, tid, warp, l16, lh);

        // epilogue: +bias, srms over 512 cols (cross-warp), relu, -> nxt (fp16)
        float ssA = 0.0f, ssB = 0.0f;
        #pragma unroll
        for (int nt = 0; nt < 8; nt++) {
            float2 bv = *(const float2*)(bg + warp * 64 + nt * 8 + 2 * t4);
            acc[nt][0] += bv.x; acc[nt][1] += bv.y;
            acc[nt][2] += bv.x; acc[nt][3] += bv.y;
            ssA += acc[nt][0] * acc[nt][0] + acc[nt][1] * acc[nt][1];
            ssB += acc[nt][2] * acc[nt][2] + acc[nt][3] * acc[nt][3];
        }
        ssA += __shfl_xor_sync(0xffffffffu, ssA, 1);
        ssA += __shfl_xor_sync(0xffffffffu, ssA, 2);
        ssB += __shfl_xor_sync(0xffffffffu, ssB, 1);
        ssB += __shfl_xor_sync(0xffffffffu, ssB, 2);
        __syncthreads();
        if (t4 == 0) {
            red[g * 8 + warp] = ssA;
            red[(g + 8) * 8 + warp] = ssB;
        }
        __syncthreads();
        float totA = 0.0f, totB = 0.0f;
        #pragma unroll
        for (int w2 = 0; w2 < 8; w2++) { totA += red[g * 8 + w2]; totB += red[(g + 8) * 8 + w2]; }
        float invA = 1.0f / (sqrtf(totA * (1.0f / 512.0f)) + 1e-8f);
        float invB = 1.0f / (sqrtf(totB * (1.0f / 512.0f)) + 1e-8f);
        #pragma unroll
        for (int nt = 0; nt < 8; nt++) {
            int col = warp * 64 + nt * 8 + 2 * t4;
            __half2 ha = __floats2half2_rn(fmaxf(acc[nt][0] * invA, 0.0f),
                                           fmaxf(acc[nt][1] * invA, 0.0f));
            __half2 hb = __floats2half2_rn(fmaxf(acc[nt][2] * invB, 0.0f),
                                           fmaxf(acc[nt][3] * invB, 0.0f));
            *(uint32_t*)(nxt + g * CSTR + col) = *(uint32_t*)&ha;
            *(uint32_t*)(nxt + (g + 8) * CSTR + col) = *(uint32_t*)&hb;
        }
        __syncthreads();
        __half* tmp = cur; cur = nxt; nxt = tmp;
    }

    // ---- final layer (Wz, N=1024): two 512-col passes + decay -> arr -------
    int rA = t0 + g, rB = t0 + g + 8;
    float decA = (rA == 0) ? 1.0f : expf((float)rA * lg);
    float decB = expf((float)rB * lg);
    #pragma unroll 1
    for (int nb = 0; nb < 2; nb++) {
        float acc[8][4];
        #pragma unroll
        for (int nt = 0; nt < 8; nt++)
            #pragma unroll
            for (int e = 0; e < 4; e++) acc[nt][e] = 0.0f;

        coef_gemm(smem_u32(cur), Wzh, 1024, nb * 512, bsBase, acc, tid, warp, l16, lh);

        #pragma unroll
        for (int nt = 0; nt < 8; nt++) {
            int col = nb * 512 + warp * 64 + nt * 8 + 2 * t4;
            float2 bv = *(const float2*)(bz + col);
            float2 oa = make_float2(decA * (acc[nt][0] + bv.x), decA * (acc[nt][1] + bv.y));
            float2 ob = make_float2(decB * (acc[nt][2] + bv.x), decB * (acc[nt][3] + bv.y));
            *(float2*)(arr + (size_t)rA * D1 + col) = oa;
            *(float2*)(arr + (size_t)rB * D1 + col) = ob;
        }
        __syncthreads();
    }
}

// ---------------- fp16 GEMM: cp.async 5-stage + ldmatrix, 128x128x32 ---------
// C[M,N] = A[M,K] @ W[K,N] + bias ; EPI: 1 silu, 3 +res
#define A_BYTES 10240               // 128*80
#define STAGE_B 18944               // A_BYTES + 32*272
#define G_STAGES 5
#define GEMM_SMEM (G_STAGES * STAGE_B)     // 94720

template <int EPI>
__device__ __forceinline__ void gemm_load_chunk(
    const __half* __restrict__ A, const __half* __restrict__ W,
    uint32_t sbase, int st, int i, int nch, int m0, int n0, int N, int K, int tid) {
    if (i < nch) {
        int k0 = i << 5;
        uint32_t sb = sbase + st * STAGE_B;
        #pragma unroll
        for (int j = 0; j < 2; j++) {
            int idx = j * 256 + tid;          // 0..511
            int rowa = idx >> 2;              // 0..127
            int sega = idx & 3;
            uint32_t dst = sb + rowa * 80 + sega * 16;
            const __half* src = A + (size_t)(m0 + rowa) * K + k0 + sega * 8;
            CP_ASYNC16(dst, src);
        }
        #pragma unroll
        for (int j = 0; j < 2; j++) {
            int idx = j * 256 + tid;
            int rowb = idx >> 4;              // 0..31
            int nseg = idx & 15;
            uint32_t dst = sb + A_BYTES + rowb * 272 + nseg * 16;
            const __half* src = W + (size_t)(k0 + rowb) * N + n0 + nseg * 8;
            CP_ASYNC16(dst, src);
        }
    }
    CP_COMMIT();
}

template <int EPI>
__global__ void __launch_bounds__(256)
hgemm_kernel(const __half* __restrict__ A, const __half* __restrict__ W,
             const float* __restrict__ bias, const float* __restrict__ res,
             float* __restrict__ C, int M, int N, int K) {
    extern __shared__ __align__(16) uint8_t smraw[];
    uint32_t sbase = smem_u32(smraw);

    int tid = threadIdx.x;             // 256
    int n0 = blockIdx.x * 128;
    int m0 = blockIdx.y * 128;
    int warp = tid >> 5, lane = tid & 31;
    int wm = warp >> 2;                // 0..1  (64-row slab)
    int wn = warp & 3;                 // 0..3  (32-col slab)
    int g = lane >> 2, t = lane & 3;
    int l16 = lane & 15, lh = lane >> 4;

    float acc[4][4][4];
    #pragma unroll
    for (int mt = 0; mt < 4; mt++)
        #pragma unroll
        for (int nt = 0; nt < 4; nt++)
            #pragma unroll
            for (int e = 0; e < 4; e++) acc[mt][nt][e] = 0.0f;

    int nch = K >> 5;
    gemm_load_chunk<EPI>(A, W, sbase, 0, 0, nch, m0, n0, N, K, tid);
    gemm_load_chunk<EPI>(A, W, sbase, 1, 1, nch, m0, n0, N, K, tid);
    gemm_load_chunk<EPI>(A, W, sbase, 2, 2, nch, m0, n0, N, K, tid);
    gemm_load_chunk<EPI>(A, W, sbase, 3, 3, nch, m0, n0, N, K, tid);

    #pragma unroll 1
    for (int i = 0; i < nch; i++) {
        CP_WAIT3();
        __syncthreads();
        gemm_load_chunk<EPI>(A, W, sbase, (i + 4) % G_STAGES, i + 4, nch, m0, n0, N, K, tid);

        int st = i % G_STAGES;
        uint32_t sA = sbase + st * STAGE_B;
        uint32_t sB = sA + A_BYTES;

        #pragma unroll
        for (int ks = 0; ks < 2; ks++) {
            uint32_t af[4][4], bf[4][2];
            #pragma unroll
            for (int mt = 0; mt < 4; mt++) {
                int row = wm * 64 + mt * 16 + l16;
                uint32_t addr = sA + row * 80 + (ks * 2 + lh) * 16;
                LDSM_X4(af[mt][0], af[mt][1], af[mt][2], af[mt][3], addr);
            }
            #pragma unroll
            for (int p = 0; p < 2; p++) {
                int rowb = ks * 16 + l16;
                int nseg = wn * 4 + p * 2 + lh;
                uint32_t addr = sB + rowb * 272 + nseg * 16;
                LDSM_X4T(bf[2 * p][0], bf[2 * p][1], bf[2 * p + 1][0], bf[2 * p + 1][1], addr);
            }
            #pragma unroll
            for (int mt = 0; mt < 4; mt++)
                #pragma unroll
                for (int nt = 0; nt < 4; nt++)
                    MMA_F16(acc[mt][nt], af[mt], bf[nt]);
        }
    }

    #pragma unroll
    for (int mt = 0; mt < 4; mt++) {
        int mrow0 = m0 + wm * 64 + mt * 16 + g;
        #pragma unroll
        for (int h2 = 0; h2 < 2; h2++) {
            int m = mrow0 + 8 * h2;
            #pragma unroll
            for (int nt = 0; nt < 4; nt++) {
                int n = n0 + wn * 32 + nt * 8 + 2 * t;
                float v0 = acc[mt][nt][2 * h2 + 0] + bias[n];
                float v1 = acc[mt][nt][2 * h2 + 1] + bias[n + 1];
                if (EPI == 1) {
                    v0 = v0 / (1.0f + expf(-v0));
                    v1 = v1 / (1.0f + expf(-v1));
                }
                if (EPI == 3) {
                    float2 rv = *(const float2*)(res + (size_t)m * N + n);
                    v0 += rv.x; v1 += rv.y;
                }
                *(float2*)(C + (size_t)m * N + n) = make_float2(v0, v1);
            }
        }
    }
}

// ---------------- causal depthwise Toeplitz conv + gate ----------------------
// Circular 256-row v window: only 64 new rows loaded per chunk (192 on first).
#define CONV_SMEM ((64 * 64 + 256 * 64) * 4)   // 81920

__global__ void __launch_bounds__(256)
conv_kernel(const float* __restrict__ v, const float* __restrict__ arr,
            const float* __restrict__ u, __half* __restrict__ yh) {
    extern __shared__ float cs[];
    float* a_s = cs;              // [64][64]
    float* v_s = cs + 64 * 64;    // [256][64] circular by global row & 255

    int b = blockIdx.z;
    int c0 = blockIdx.y * 64;
    int iblk = (gridDim.x - 1) - blockIdx.x;   // heaviest tiles first
    int t0 = iblk * 128;
    int tid = threadIdx.x;                     // 256
    int tx = tid & 15;                         // c group (4 channels)
    int ty = tid >> 4;                         // t group (8 rows)

    unsigned long long acc2[8][2];
    #pragma unroll
    for (int i = 0; i < 8; i++) { acc2[i][0] = 0ULL; acc2[i][1] = 0ULL; }

    const float* vb = v + (size_t)b * NTOK * D1;
    int nch = 2 * iblk + 2;

    for (int jb = 0; jb < nch; jb++) {
        __syncthreads();
        // a chunk: rows jb*64..+63, cols c0..c0+63
        #pragma unroll
        for (int it = 0; it < 4; it++) {
            int idx = it * 256 + tid;
            int rq = idx >> 4;
            int cseg = idx & 15;
            float4 val = *(const float4*)(arr + (size_t)(jb * 64 + rq) * D1 + c0 + cseg * 4);
            *(float4*)(&a_s[rq * 64 + cseg * 4]) = val;
        }
        // v rows: window low = t0 - jb*64 - 63; load 64 new rows (192 if jb==0)
        int wlo = t0 - jb * 64 - 63;
        int ngrp = (jb == 0) ? 3 : 1;
        for (int grp = 0; grp < ngrp; grp++) {
            #pragma unroll
            for (int it = 0; it < 4; it++) {
                int idx = it * 256 + tid;      // 0..1023
                int rl = idx >> 4;             // 0..63
                int cseg = idx & 15;
                int gg = wlo + grp * 64 + rl;
                int slot = (gg + 1024) & 255;
                float4 val = make_float4(0.0f, 0.0f, 0.0f, 0.0f);
                if (gg >= 0 && gg < NTOK)
                    val = *(const float4*)(vb + (size_t)gg * D1 + c0 + cseg * 4);
                *(float4*)(&v_s[slot * 64 + cseg * 4]) = val;
            }
        }
        __syncthreads();

        // register sliding window; global row base for q=0
        int base = t0 - jb * 64 + 1024 + ty * 8;
        unsigned long long w2[8][2];
        #pragma unroll
        for (int i = 0; i < 8; i++) {
            int slot = (base + i) & 255;
            ulonglong2 wv = *(const ulonglong2*)(&v_s[slot * 64 + tx * 4]);
            w2[i][0] = wv.x; w2[i][1] = wv.y;
        }

        #pragma unroll 8
        for (int q = 0; q < 64; q++) {
            ulonglong2 a2 = *(const ulonglong2*)(&a_s[q * 64 + tx * 4]);
            #pragma unroll
            for (int i = 0; i < 8; i++) {
                FFMA2(acc2[i][0], a2.x, w2[i][0], acc2[i][0]);
                FFMA2(acc2[i][1], a2.y, w2[i][1], acc2[i][1]);
            }
            if (q < 63) {
                #pragma unroll
                for (int i = 7; i > 0; i--) { w2[i][0] = w2[i - 1][0]; w2[i][1] = w2[i - 1][1]; }
                int slot = (base - 1 - q) & 255;
                ulonglong2 wv = *(const ulonglong2*)(&v_s[slot * 64 + tx * 4]);
                w2[0][0] = wv.x; w2[0][1] = wv.y;
            }
        }
    }

    #pragma unroll
    for (int i = 0; i < 8; i++) {
        int t = t0 + ty * 8 + i;
        size_t off = ((size_t)b * NTOK + t) * D1 + c0 + tx * 4;
        float4 uv = *(const float4*)(u + off);
        float2 lo = *(float2*)(&acc2[i][0]);
        float2 hi = *(float2*)(&acc2[i][1]);
        __half2 ha = __floats2half2_rn(uv.x * lo.x, uv.y * lo.y);
        __half2 hb = __floats2half2_rn(uv.z * hi.x, uv.w * hi.y);
        *(uint2*)(yh + off) = make_uint2(*(uint32_t*)&ha, *(uint32_t*)&hb);
    }
}

// ---------------- launch ----------------
extern "C" void kernel_launch(void* const* d_in, const int* in_sizes, int n_in,
                              void* d_out, int out_size) {
    const float* x  = (const float*)d_in[0];
    const float* Wu = (const float*)d_in[1];
    const float* bu = (const float*)d_in[2];
    const float* Wv = (const float*)d_in[3];
    const float* bv = (const float*)d_in[4];
    const float* Wo = (const float*)d_in[5];
    const float* bo = (const float*)d_in[6];
    const float* Wp = (const float*)d_in[7];
    const float* bp = (const float*)d_in[8];
    const float* W1 = (const float*)d_in[9];
    const float* b1 = (const float*)d_in[10];
    const float* W2 = (const float*)d_in[11];
    const float* b2 = (const float*)d_in[12];
    const float* W3 = (const float*)d_in[13];
    const float* b3 = (const float*)d_in[14];
    const float* Wz = (const float*)d_in[15];
    const float* bz = (const float*)d_in[16];
    float* out = (float*)d_out;

    float *u, *v, *arr;
    __half *xnh, *yh, *Wuh, *Wvh, *Woh, *W1h, *W2h, *W3h, *Wzh;
    cudaGetSymbolAddress((void**)&u,    g_u);
    cudaGetSymbolAddress((void**)&v,    g_v);
    cudaGetSymbolAddress((void**)&arr,  g_arr);
    cudaGetSymbolAddress((void**)&xnh,  g_xnh);
    cudaGetSymbolAddress((void**)&yh,   g_yh);
    cudaGetSymbolAddress((void**)&Wuh,  g_Wuh);
    cudaGetSymbolAddress((void**)&Wvh,  g_Wvh);
    cudaGetSymbolAddress((void**)&Woh,  g_Woh);
    cudaGetSymbolAddress((void**)&W1h,  g_W1h);
    cudaGetSymbolAddress((void**)&W2h,  g_W2h);
    cudaGetSymbolAddress((void**)&W3h,  g_W3h);
    cudaGetSymbolAddress((void**)&Wzh,  g_Wzh);

    cudaFuncSetAttribute(hgemm_kernel<1>, cudaFuncAttributeMaxDynamicSharedMemorySize, GEMM_SMEM);
    cudaFuncSetAttribute(hgemm_kernel<3>, cudaFuncAttributeMaxDynamicSharedMemorySize, GEMM_SMEM);
    cudaFuncSetAttribute(conv_kernel,     cudaFuncAttributeMaxDynamicSharedMemorySize, CONV_SMEM);
    cudaFuncSetAttribute(coef_mlp_kernel, cudaFuncAttributeMaxDynamicSharedMemorySize, COEF_SMEM);

    // all weight conversions in one launch
    f2h_all_kernel<<<2816, 256>>>(Wu, Wv, Wo, W1, W2, W3, Wz,
                                  Wuh, Wvh, Woh, W1h, W2h, W3h, Wzh);

    // main path norm -> fp16
    srms_kernel<<<ROWS, 128>>>(x, xnh);

    // fused position-coefficient MLP -> arr (with decay)
    coef_mlp_kernel<<<NTOK / 16, 256, COEF_SMEM>>>(Wp, bp, W1h, b1, W2h, b2,
                                                   W3h, b3, Wzh, bz, arr);

    // u, v projections with SiLU
    hgemm_kernel<1><<<dim3(D1 / 128, ROWS / 128), 256, GEMM_SMEM>>>(xnh, Wuh, bu, nullptr, u, ROWS, D1, DDIM);
    hgemm_kernel<1><<<dim3(D1 / 128, ROWS / 128), 256, GEMM_SMEM>>>(xnh, Wvh, bv, nullptr, v, ROWS, D1, DDIM);

    // causal depthwise Toeplitz conv, gated by u -> fp16 y
    conv_kernel<<<dim3(NTOK / 128, D1 / 64, NB), 256, CONV_SMEM>>>(v, arr, u, yh);

    // output projection + bias + residual
    hgemm_kernel<3><<<dim3(DDIM / 128, ROWS / 128), 256, GEMM_SMEM>>>(yh, Woh, bo, x, out, ROWS, DDIM, D1);
}